// round 5
// baseline (speedup 1.0000x reference)
#include <cuda_runtime.h>
#include <cuda_bf16.h>
#include <math.h>

typedef unsigned long long ull;
typedef unsigned int u32;

// Problem constants
#define NB   16
#define CIN  128
#define COUT 128
#define HH   64
#define WW   64
#define HO   64
#define WO   64
#define PP   9
#define HW   (HH*WW)
#define PIX_PER_N (HO*WO)

#define ROWB 272   // smem row stride in bytes (136 bf16 = 17*16B, conflict-free ldmatrix)

// ---------------- scratch ----------------
__device__ float  g_xT[NB * HH * WW * CIN];                    // NHWC x (fp32)
__device__ float4 g_meta[NB * PP * HO * WO];                   // y0,x0(bitcast),wy,wx
__device__ __align__(16) __nv_bfloat16 g_wh[PP * COUT * CIN];  // [p][cout][cin] hi
__device__ __align__(16) __nv_bfloat16 g_wl[PP * COUT * CIN];  // lo

// ---------------- packed f32x2 helpers (offset conv) ----------------
__device__ __forceinline__ void fma2(ull& d, ull a, ull b) {
    asm("fma.rn.f32x2 %0, %1, %2, %0;" : "+l"(d) : "l"(a), "l"(b));
}
__device__ __forceinline__ void add2(ull& d, ull a, ull b) {
    asm("add.rn.f32x2 %0, %1, %2;" : "=l"(d) : "l"(a), "l"(b));
}
__device__ __forceinline__ ull bcast2(float a) {
    ull r; asm("mov.b64 %0, {%1, %1};" : "=l"(r) : "f"(a)); return r;
}
__device__ __forceinline__ ull pack2(float lo, float hi) {
    ull r; asm("mov.b64 %0, {%1, %2};" : "=l"(r) : "f"(lo), "f"(hi)); return r;
}
__device__ __forceinline__ void unpack2(ull v, float& lo, float& hi) {
    asm("mov.b64 {%0, %1}, %2;" : "=f"(lo), "=f"(hi) : "l"(v));
}

// ---------------- mma helpers ----------------
__device__ __forceinline__ u32 cvta_smem(const void* p) {
    u32 r;
    asm("{ .reg .u64 t; cvta.to.shared.u64 t, %1; cvt.u32.u64 %0, t; }" : "=r"(r) : "l"(p));
    return r;
}
__device__ __forceinline__ void ldm4(u32* r, u32 addr) {
    asm volatile("ldmatrix.sync.aligned.m8n8.x4.shared.b16 {%0,%1,%2,%3}, [%4];"
                 : "=r"(r[0]), "=r"(r[1]), "=r"(r[2]), "=r"(r[3]) : "r"(addr));
}
__device__ __forceinline__ void mma_bf16(float* c, const u32* a, u32 b0, u32 b1) {
    asm volatile("mma.sync.aligned.m16n8k16.row.col.f32.bf16.bf16.f32 "
                 "{%0,%1,%2,%3}, {%4,%5,%6,%7}, {%8,%9}, {%0,%1,%2,%3};"
                 : "+f"(c[0]), "+f"(c[1]), "+f"(c[2]), "+f"(c[3])
                 : "r"(a[0]), "r"(a[1]), "r"(a[2]), "r"(a[3]), "r"(b0), "r"(b1));
}
__device__ __forceinline__ void cp_async16(u32 dst, const void* src) {
    asm volatile("cp.async.cg.shared.global [%0], [%1], 16;" :: "r"(dst), "l"(src));
}
#define CP_COMMIT()  asm volatile("cp.async.commit_group;" ::: "memory")
#define CP_WAIT(n)   asm volatile("cp.async.wait_group %0;" :: "n"(n) : "memory")

// ---------------- kernel 1: x NCHW -> NHWC ----------------
__global__ void k_transpose_x(const float* __restrict__ x) {
    __shared__ float tile[32][33];
    int n   = blockIdx.z;
    int hw0 = blockIdx.x * 32;
    int c0  = blockIdx.y * 32;
    int tx = threadIdx.x, ty = threadIdx.y;
    #pragma unroll
    for (int i = 0; i < 32; i += 8)
        tile[ty + i][tx] = x[((size_t)(n * CIN + c0 + ty + i)) * HW + hw0 + tx];
    __syncthreads();
    #pragma unroll
    for (int i = 0; i < 32; i += 8)
        g_xT[((size_t)(n * HW + hw0 + ty + i)) * CIN + c0 + tx] = tile[tx][ty + i];
}

// ---------------- kernel 2: deform_w -> bf16 hi/lo [p][cout][cin] ----------------
__global__ void k_prep_w(const float* __restrict__ w) {
    int i = blockIdx.x * 256 + threadIdx.x;
    if (i >= PP * COUT * CIN) return;
    int cin  = i & 127;
    int cout = (i >> 7) & 127;
    int p    = i >> 14;
    float v = w[(cout * CIN + cin) * PP + p];
    __nv_bfloat16 h = __float2bfloat16_rn(v);
    g_wh[i] = h;
    g_wl[i] = __float2bfloat16_rn(v - __bfloat162float(h));
}

// ---------------- kernel 3: offset conv (f32x2) + bilinear metadata ----------------
__global__ void k_offset_meta(const float* __restrict__ offset_w,
                              const float* __restrict__ offset_b) {
    extern __shared__ float sm_[];
    ull*   wsh2 = (ull*)sm_;                         // 9*9*128 ull
    float* ash  = sm_ + 2 * 9 * 9 * CIN;             // 8 warps * 72 floats

    int tid = threadIdx.x;
    for (int i = tid; i < PP * 9 * CIN; i += blockDim.x) {
        int cin = i & 127;
        int q   = (i >> 7) % 9;
        int p   = i / (9 * CIN);
        float lo = offset_w[((2 * q)     * CIN + cin) * PP + p];
        float hi = offset_w[((2 * q + 1) * CIN + cin) * PP + p];
        wsh2[i] = pack2(lo, hi);
    }
    __syncthreads();

    int lane = tid & 31;
    int warp = tid >> 5;
    int gw   = blockIdx.x * 8 + warp;
    int pb   = gw * 4;
    int n    = pb >> 12;
    int r    = pb & 4095;
    int ho   = r >> 6;
    int wo0  = r & 63;

    ull acc2[4][9];
    #pragma unroll
    for (int j = 0; j < 4; j++)
        #pragma unroll
        for (int q = 0; q < 9; q++) acc2[j][q] = 0ull;

    const float* xn = g_xT + (size_t)n * HW * CIN;

    #pragma unroll
    for (int p = 0; p < PP; p++) {
        int ky = p / 3, kx = p % 3;
        int ih = ho + ky - 1;
        bool vrow = (unsigned)ih < (unsigned)HH;
        #pragma unroll
        for (int cc = 0; cc < 4; cc++) {
            int cin = cc * 32 + lane;
            ull xb[4];
            #pragma unroll
            for (int j = 0; j < 4; j++) {
                int iw = wo0 + j + kx - 1;
                bool v = vrow && ((unsigned)iw < (unsigned)WW);
                float xv = v ? xn[((size_t)(ih * WW + iw)) * CIN + cin] : 0.f;
                xb[j] = bcast2(xv);
            }
            const ull* wrow = wsh2 + p * (9 * CIN) + cin;
            #pragma unroll
            for (int q = 0; q < 9; q++) {
                ull wq = wrow[q * CIN];
                fma2(acc2[0][q], xb[0], wq);
                fma2(acc2[1][q], xb[1], wq);
                fma2(acc2[2][q], xb[2], wq);
                fma2(acc2[3][q], xb[3], wq);
            }
        }
    }

    #pragma unroll
    for (int off = 16; off > 0; off >>= 1)
        #pragma unroll
        for (int j = 0; j < 4; j++)
            #pragma unroll
            for (int q = 0; q < 9; q++) {
                ull o = __shfl_down_sync(0xffffffffu, acc2[j][q], off);
                add2(acc2[j][q], acc2[j][q], o);
            }

    float* aw = ash + warp * 72;
    if (lane == 0) {
        #pragma unroll
        for (int j = 0; j < 4; j++)
            #pragma unroll
            for (int q = 0; q < 9; q++) {
                float lo, hi;
                unpack2(acc2[j][q], lo, hi);
                aw[j * 18 + 2 * q]     = lo;
                aw[j * 18 + 2 * q + 1] = hi;
            }
    }
    __syncwarp();

    for (int item = lane; item < 36; item += 32) {
        int j = item / 9;
        int p = item % 9;
        int ky = p / 3, kx = p % 3;
        float dy = aw[j * 18 + 2 * p]     + offset_b[2 * p];
        float dx = aw[j * 18 + 2 * p + 1] + offset_b[2 * p + 1];
        float py = dy + (float)ky + (float)(ho - 1);
        float px = dx + (float)kx + (float)(wo0 + j - 1);
        float y0f = floorf(py);
        float x0f = floorf(px);
        g_meta[((size_t)(n * PP + p)) * PIX_PER_N + ho * WO + wo0 + j] =
            make_float4(__int_as_float((int)y0f), __int_as_float((int)x0f),
                        py - y0f, px - x0f);
    }
}

// ---------------- kernel 4: pipelined gather + bf16 split mma GEMM + BN + SiLU ----------
// smem layout (bytes):
//   BsH [0, 34816)        BsL [34816, 69632)
//   As buf0: H [69632,104448) L [104448,139264)
//   As buf1: H [139264,174080) L [174080,208896)
//   msh [208896, 227328)  ssh [227328,+512)  bsh [227840,+512)
#define OFF_BSH 0
#define OFF_BSL 34816
#define OFF_AS  69632
#define ASBUF   69632
#define OFF_MSH 208896
#define OFF_SSH 227328
#define OFF_BBH 227840
#define SMEM_MAIN 228352

struct GBuf {
    float2 c00[2], c01[2], c10[2], c11[2];
    float w00, w01, w10, w11;
    int pix;
};

__device__ __forceinline__ void g_issue(GBuf& g, const float4* msh, int p1, int pix,
                                        const float* xn, int lane) {
    g.pix = pix;
    float4 m = msh[p1 * 128 + pix];
    int y0 = __float_as_int(m.x);
    int x0 = __float_as_int(m.y);
    float wy = m.z, wx = m.w;
    g.w00 = (1.f - wy) * (1.f - wx);
    g.w01 = (1.f - wy) * wx;
    g.w10 = wy * (1.f - wx);
    g.w11 = wy * wx;
    bool vy0 = (unsigned)y0       < (unsigned)HH;
    bool vy1 = (unsigned)(y0 + 1) < (unsigned)HH;
    bool vx0 = (unsigned)x0       < (unsigned)WW;
    bool vx1 = (unsigned)(x0 + 1) < (unsigned)WW;
    const float* r0 = xn + (long long)y0 * (WW * CIN);
    const float* r1 = r0 + WW * CIN;
    float2 z = make_float2(0.f, 0.f);
    #pragma unroll
    for (int cc = 0; cc < 2; cc++) {
        int ch0 = cc * 64 + lane * 2;
        g.c00[cc] = (vy0 && vx0) ? *(const float2*)&r0[x0 * CIN + ch0]       : z;
        g.c01[cc] = (vy0 && vx1) ? *(const float2*)&r0[(x0 + 1) * CIN + ch0] : z;
        g.c10[cc] = (vy1 && vx0) ? *(const float2*)&r1[x0 * CIN + ch0]       : z;
        g.c11[cc] = (vy1 && vx1) ? *(const float2*)&r1[(x0 + 1) * CIN + ch0] : z;
    }
}
__device__ __forceinline__ void g_consume(GBuf& g, char* AsH, char* AsL, int lane) {
    #pragma unroll
    for (int cc = 0; cc < 2; cc++) {
        float v0 = g.w00 * g.c00[cc].x + g.w01 * g.c01[cc].x
                 + g.w10 * g.c10[cc].x + g.w11 * g.c11[cc].x;
        float v1 = g.w00 * g.c00[cc].y + g.w01 * g.c01[cc].y
                 + g.w10 * g.c10[cc].y + g.w11 * g.c11[cc].y;
        __nv_bfloat16 h0 = __float2bfloat16_rn(v0);
        __nv_bfloat16 h1 = __float2bfloat16_rn(v1);
        __nv_bfloat16 l0 = __float2bfloat16_rn(v0 - __bfloat162float(h0));
        __nv_bfloat16 l1 = __float2bfloat16_rn(v1 - __bfloat162float(h1));
        u32 uh = (u32)__bfloat16_as_ushort(h0) | ((u32)__bfloat16_as_ushort(h1) << 16);
        u32 ul = (u32)__bfloat16_as_ushort(l0) | ((u32)__bfloat16_as_ushort(l1) << 16);
        int off = g.pix * ROWB + cc * 128 + lane * 4;
        *(u32*)(AsH + off) = uh;
        *(u32*)(AsL + off) = ul;
    }
}

// full-tap gather (prologue only)
__device__ __forceinline__ void gather_tap(int p, int gpix0, int lane,
                                           const float4* msh, const float* xn,
                                           char* AsH, char* AsL) {
    #pragma unroll
    for (int pl = 0; pl < 8; pl++) {
        GBuf g;
        g_issue(g, msh, p, gpix0 + pl, xn, lane);
        g_consume(g, AsH, AsL, lane);
    }
}

__device__ __forceinline__ void copy_bs(const __nv_bfloat16* src_g, u32 dst_u, int tid) {
    const char* src = (const char*)src_g;
    #pragma unroll
    for (int i = 0; i < 4; i++) {              // 2048 16B-chunks / 512 thr
        int c   = tid + i * 512;
        int row = c >> 4;
        int c16 = c & 15;
        cp_async16(dst_u + (u32)(row * ROWB + c16 * 16), src + row * 256 + c16 * 16);
    }
}

__global__ __launch_bounds__(512, 1)
void k_main(const float* __restrict__ gamma,
            const float* __restrict__ beta,
            const float* __restrict__ rmean,
            const float* __restrict__ rvar,
            float* __restrict__ out) {
    extern __shared__ char smc[];
    float4* msh = (float4*)(smc + OFF_MSH);
    float*  ssh = (float*)(smc + OFF_SSH);
    float*  bsh = (float*)(smc + OFF_BBH);
    u32 sbase = cvta_smem(smc);
    u32 bsHu = sbase + OFF_BSH, bsLu = sbase + OFF_BSL;
    u32 asu  = sbase + OFF_AS;

    int tid  = threadIdx.x;
    int ho0  = blockIdx.x * 2;
    int n    = blockIdx.y;
    int lane = tid & 31;
    int warp = tid >> 5;
    int wm   = warp >> 2;
    int wn   = warp & 3;
    int gpix0 = warp * 8;

    for (int i = tid; i < PP * 128; i += 512) {
        int p   = i >> 7;
        int pix = i & 127;
        int row = ho0 + (pix >> 6);
        int wo  = pix & 63;
        msh[i] = g_meta[((size_t)(n * PP + p)) * PIX_PER_N + row * WO + wo];
    }
    if (tid < COUT) {
        float s = gamma[tid] * rsqrtf(rvar[tid] + 1e-5f);
        ssh[tid] = s;
        bsh[tid] = beta[tid] - rmean[tid] * s;
    }
    __syncthreads();

    const float* xn = g_xT + (size_t)n * HW * CIN;

    // prologue: Bs(0) (one group) + direct gather of tap 0 into buf 0
    copy_bs(g_wl, bsLu, tid);
    copy_bs(g_wh, bsHu, tid);
    CP_COMMIT();
    gather_tap(0, gpix0, lane, msh, xn, smc + OFF_AS, smc + OFF_AS + 34816);
    CP_WAIT(0);
    __syncthreads();

    float acc[2][4][4];
    #pragma unroll
    for (int mt = 0; mt < 2; mt++)
        #pragma unroll
        for (int nt = 0; nt < 4; nt++)
            #pragma unroll
            for (int i = 0; i < 4; i++) acc[mt][nt][i] = 0.f;

    int lrow = lane & 15;
    int lcol = (lane >> 4) << 4;
    int cur = 0;

    for (int p = 0; p < PP; p++) {
        bool pref = (p < PP - 1);
        u32 asb   = asu + cur * ASBUF;                    // AsH cur
        char* nAsH = smc + OFF_AS + (cur ^ 1) * ASBUF;
        char* nAsL = nAsH + 34816;

        GBuf g0, g1;
        int cons = 0;
        if (pref) {
            g_issue(g0, msh, p + 1, gpix0 + 0, xn, lane);
            g_issue(g1, msh, p + 1, gpix0 + 1, xn, lane);
        }

        // ---- phase 1: acc += Ah * Bl ----
        #pragma unroll
        for (int ks = 0; ks < 8; ks++) {
            u32 k0b = (u32)(ks * 32 + lcol);
            u32 ah[2][4], bl[2][4];
            #pragma unroll
            for (int mt = 0; mt < 2; mt++)
                ldm4(ah[mt], asb + (u32)((wm * 32 + mt * 16 + lrow) * ROWB) + k0b);
            #pragma unroll
            for (int pr = 0; pr < 2; pr++)
                ldm4(bl[pr], bsLu + (u32)((wn * 32 + pr * 16 + lrow) * ROWB) + k0b);
            #pragma unroll
            for (int mt = 0; mt < 2; mt++)
                #pragma unroll
                for (int nt = 0; nt < 4; nt++) {
                    int pr = nt >> 1, s = nt & 1;
                    mma_bf16(acc[mt][nt], ah[mt], bl[pr][s], bl[pr][2 + s]);
                }
            if (pref && (ks & 1)) {
                GBuf& gc = (cons & 1) ? g1 : g0;
                g_consume(gc, nAsH, nAsL, lane);
                if (cons + 2 < 8) g_issue(gc, msh, p + 1, gpix0 + cons + 2, xn, lane);
                cons++;
            }
        }

        __syncthreads();                         // everyone done reading BsL(p)
        if (pref) { copy_bs(g_wl + (size_t)(p + 1) * COUT * CIN, bsLu, tid); CP_COMMIT(); CP_WAIT(1); }
        else      { CP_WAIT(0); }                // ensure BsH(p) landed
        __syncthreads();

        // ---- phase 2: acc += Ah * Bh + Al * Bh ----
        #pragma unroll
        for (int ks = 0; ks < 8; ks++) {
            u32 k0b = (u32)(ks * 32 + lcol);
            u32 ah[2][4], al[2][4], bh[2][4];
            #pragma unroll
            for (int mt = 0; mt < 2; mt++) {
                u32 ra = asb + (u32)((wm * 32 + mt * 16 + lrow) * ROWB) + k0b;
                ldm4(ah[mt], ra);
                ldm4(al[mt], ra + 34816);
            }
            #pragma unroll
            for (int pr = 0; pr < 2; pr++)
                ldm4(bh[pr], bsHu + (u32)((wn * 32 + pr * 16 + lrow) * ROWB) + k0b);
            #pragma unroll
            for (int mt = 0; mt < 2; mt++)
                #pragma unroll
                for (int nt = 0; nt < 4; nt++) {
                    int pr = nt >> 1, s = nt & 1;
                    mma_bf16(acc[mt][nt], ah[mt], bh[pr][s], bh[pr][2 + s]);
                    mma_bf16(acc[mt][nt], al[mt], bh[pr][s], bh[pr][2 + s]);
                }
            if (pref && (ks & 1)) {
                GBuf& gc = (cons & 1) ? g1 : g0;
                g_consume(gc, nAsH, nAsL, lane);
                if (cons + 2 < 8) g_issue(gc, msh, p + 1, gpix0 + cons + 2, xn, lane);
                cons++;
            }
        }

        __syncthreads();                         // done reading BsH(p) + As(cur)
        if (pref) { copy_bs(g_wh + (size_t)(p + 1) * COUT * CIN, bsHu, tid); CP_COMMIT(); CP_WAIT(1); }
        __syncthreads();
        cur ^= 1;
    }

    // ---- epilogue: BN + SiLU ----
    #pragma unroll
    for (int mt = 0; mt < 2; mt++)
        #pragma unroll
        for (int nt = 0; nt < 4; nt++) {
            int co = wn * 32 + nt * 8 + (lane & 3) * 2;
            int px = wm * 32 + mt * 16 + (lane >> 2);
            float s0 = ssh[co],     b0 = bsh[co];
            float s1 = ssh[co + 1], b1 = bsh[co + 1];
            #pragma unroll
            for (int h = 0; h < 2; h++) {
                int pr_ = px + h * 8;
                int row = ho0 + (pr_ >> 6);
                int wo  = pr_ & 63;
                float y0v = acc[mt][nt][h * 2 + 0] * s0 + b0;
                float y1v = acc[mt][nt][h * 2 + 1] * s1 + b1;
                out[(((size_t)(n * COUT + co))     * HO + row) * WO + wo] = y0v / (1.f + expf(-y0v));
                out[(((size_t)(n * COUT + co + 1)) * HO + row) * WO + wo] = y1v / (1.f + expf(-y1v));
            }
        }
}

// ---------------- launch ----------------
extern "C" void kernel_launch(void* const* d_in, const int* in_sizes, int n_in,
                              void* d_out, int out_size) {
    const float* x        = (const float*)d_in[0];
    const float* offset_w = (const float*)d_in[1];
    const float* offset_b = (const float*)d_in[2];
    const float* deform_w = (const float*)d_in[3];
    const float* gamma    = (const float*)d_in[4];
    const float* beta     = (const float*)d_in[5];
    const float* rmean    = (const float*)d_in[6];
    const float* rvar     = (const float*)d_in[7];
    float* out = (float*)d_out;

    cudaFuncSetAttribute(k_offset_meta, cudaFuncAttributeMaxDynamicSharedMemorySize, 90000);
    cudaFuncSetAttribute(k_main,        cudaFuncAttributeMaxDynamicSharedMemorySize, SMEM_MAIN);

    k_transpose_x<<<dim3(HW / 32, CIN / 32, NB), dim3(32, 8)>>>(x);
    k_prep_w<<<(PP * COUT * CIN + 255) / 256, 256>>>(deform_w);

    size_t sm3 = (size_t)(PP * 9 * CIN) * 8 + (size_t)(8 * 72) * 4;  // 85248 B
    k_offset_meta<<<NB * PIX_PER_N / 32, 256, sm3>>>(offset_w, offset_b);

    k_main<<<dim3(HO / 2, NB), 512, SMEM_MAIN>>>(gamma, beta, rmean, rvar, out);
}

// round 6
// speedup vs baseline: 1.1818x; 1.1818x over previous
#include <cuda_runtime.h>
#include <cuda_bf16.h>
#include <math.h>

typedef unsigned long long ull;
typedef unsigned int u32;

// Problem constants
#define NB   16
#define CIN  128
#define COUT 128
#define HH   64
#define WW   64
#define HO   64
#define WO   64
#define PP   9
#define HW   (HH*WW)
#define PIX_PER_N (HO*WO)

#define ROWB 272   // smem row stride (136 bf16 = 17*16B, conflict-free ldmatrix)

// ---------------- scratch ----------------
__device__ float  g_xT[NB * HH * WW * CIN];                    // NHWC x (fp32)
__device__ float4 g_meta[NB * PP * HO * WO];                   // y0,x0(bitcast),wy,wx
__device__ __align__(16) __nv_bfloat16 g_wh[PP * COUT * CIN];  // [p][cout][cin] hi
__device__ __align__(16) __nv_bfloat16 g_wl[PP * COUT * CIN];  // lo

// ---------------- packed f32x2 helpers ----------------
__device__ __forceinline__ void fma2(ull& d, ull a, ull b) {
    asm("fma.rn.f32x2 %0, %1, %2, %0;" : "+l"(d) : "l"(a), "l"(b));
}
__device__ __forceinline__ void add2(ull& d, ull a, ull b) {
    asm("add.rn.f32x2 %0, %1, %2;" : "=l"(d) : "l"(a), "l"(b));
}
__device__ __forceinline__ ull bcast2(float a) {
    ull r; asm("mov.b64 %0, {%1, %1};" : "=l"(r) : "f"(a)); return r;
}
__device__ __forceinline__ ull pack2(float lo, float hi) {
    ull r; asm("mov.b64 %0, {%1, %2};" : "=l"(r) : "f"(lo), "f"(hi)); return r;
}
__device__ __forceinline__ void unpack2(ull v, float& lo, float& hi) {
    asm("mov.b64 {%0, %1}, %2;" : "=f"(lo), "=f"(hi) : "l"(v));
}
__device__ __forceinline__ u32 cvt_bf16x2(float hi, float lo) {   // hi->upper, lo->lower
    u32 r; asm("cvt.rn.bf16x2.f32 %0, %1, %2;" : "=r"(r) : "f"(hi), "f"(lo)); return r;
}

// ---------------- mma helpers ----------------
__device__ __forceinline__ u32 cvta_smem(const void* p) {
    u32 r;
    asm("{ .reg .u64 t; cvta.to.shared.u64 t, %1; cvt.u32.u64 %0, t; }" : "=r"(r) : "l"(p));
    return r;
}
__device__ __forceinline__ void ldm4(u32* r, u32 addr) {
    asm volatile("ldmatrix.sync.aligned.m8n8.x4.shared.b16 {%0,%1,%2,%3}, [%4];"
                 : "=r"(r[0]), "=r"(r[1]), "=r"(r[2]), "=r"(r[3]) : "r"(addr));
}
__device__ __forceinline__ void mma_bf16(float* c, const u32* a, u32 b0, u32 b1) {
    asm volatile("mma.sync.aligned.m16n8k16.row.col.f32.bf16.bf16.f32 "
                 "{%0,%1,%2,%3}, {%4,%5,%6,%7}, {%8,%9}, {%0,%1,%2,%3};"
                 : "+f"(c[0]), "+f"(c[1]), "+f"(c[2]), "+f"(c[3])
                 : "r"(a[0]), "r"(a[1]), "r"(a[2]), "r"(a[3]), "r"(b0), "r"(b1));
}
__device__ __forceinline__ void cp_async16(u32 dst, const void* src) {
    asm volatile("cp.async.cg.shared.global [%0], [%1], 16;" :: "r"(dst), "l"(src));
}
#define CP_COMMIT()  asm volatile("cp.async.commit_group;" ::: "memory")
#define CP_WAIT(n)   asm volatile("cp.async.wait_group %0;" :: "n"(n) : "memory")

// ---------------- kernel 1: x NCHW -> NHWC ----------------
__global__ void k_transpose_x(const float* __restrict__ x) {
    __shared__ float tile[32][33];
    int n   = blockIdx.z;
    int hw0 = blockIdx.x * 32;
    int c0  = blockIdx.y * 32;
    int tx = threadIdx.x, ty = threadIdx.y;
    #pragma unroll
    for (int i = 0; i < 32; i += 8)
        tile[ty + i][tx] = x[((size_t)(n * CIN + c0 + ty + i)) * HW + hw0 + tx];
    __syncthreads();
    #pragma unroll
    for (int i = 0; i < 32; i += 8)
        g_xT[((size_t)(n * HW + hw0 + ty + i)) * CIN + c0 + tx] = tile[tx][ty + i];
}

// ---------------- kernel 2: deform_w -> bf16 hi/lo [p][cout][cin] ----------------
__global__ void k_prep_w(const float* __restrict__ w) {
    int i = blockIdx.x * 256 + threadIdx.x;
    if (i >= PP * COUT * CIN) return;
    int cin  = i & 127;
    int cout = (i >> 7) & 127;
    int p    = i >> 14;
    float v = w[(cout * CIN + cin) * PP + p];
    __nv_bfloat16 h = __float2bfloat16_rn(v);
    g_wh[i] = h;
    g_wl[i] = __float2bfloat16_rn(v - __bfloat162float(h));
}

// ---------------- kernel 3: offset conv (f32x2) + bilinear metadata ----------------
__global__ void k_offset_meta(const float* __restrict__ offset_w,
                              const float* __restrict__ offset_b) {
    extern __shared__ float sm_[];
    ull*   wsh2 = (ull*)sm_;                         // 9*9*128 ull
    float* ash  = sm_ + 2 * 9 * 9 * CIN;             // 8 warps * 72 floats

    int tid = threadIdx.x;
    for (int i = tid; i < PP * 9 * CIN; i += blockDim.x) {
        int cin = i & 127;
        int q   = (i >> 7) % 9;
        int p   = i / (9 * CIN);
        float lo = offset_w[((2 * q)     * CIN + cin) * PP + p];
        float hi = offset_w[((2 * q + 1) * CIN + cin) * PP + p];
        wsh2[i] = pack2(lo, hi);
    }
    __syncthreads();

    int lane = tid & 31;
    int warp = tid >> 5;
    int gw   = blockIdx.x * 8 + warp;
    int pb   = gw * 4;
    int n    = pb >> 12;
    int r    = pb & 4095;
    int ho   = r >> 6;
    int wo0  = r & 63;

    ull acc2[4][9];
    #pragma unroll
    for (int j = 0; j < 4; j++)
        #pragma unroll
        for (int q = 0; q < 9; q++) acc2[j][q] = 0ull;

    const float* xn = g_xT + (size_t)n * HW * CIN;

    #pragma unroll
    for (int p = 0; p < PP; p++) {
        int ky = p / 3, kx = p % 3;
        int ih = ho + ky - 1;
        bool vrow = (unsigned)ih < (unsigned)HH;
        #pragma unroll
        for (int cc = 0; cc < 4; cc++) {
            int cin = cc * 32 + lane;
            ull xb[4];
            #pragma unroll
            for (int j = 0; j < 4; j++) {
                int iw = wo0 + j + kx - 1;
                bool v = vrow && ((unsigned)iw < (unsigned)WW);
                float xv = v ? xn[((size_t)(ih * WW + iw)) * CIN + cin] : 0.f;
                xb[j] = bcast2(xv);
            }
            const ull* wrow = wsh2 + p * (9 * CIN) + cin;
            #pragma unroll
            for (int q = 0; q < 9; q++) {
                ull wq = wrow[q * CIN];
                fma2(acc2[0][q], xb[0], wq);
                fma2(acc2[1][q], xb[1], wq);
                fma2(acc2[2][q], xb[2], wq);
                fma2(acc2[3][q], xb[3], wq);
            }
        }
    }

    #pragma unroll
    for (int off = 16; off > 0; off >>= 1)
        #pragma unroll
        for (int j = 0; j < 4; j++)
            #pragma unroll
            for (int q = 0; q < 9; q++) {
                ull o = __shfl_down_sync(0xffffffffu, acc2[j][q], off);
                add2(acc2[j][q], acc2[j][q], o);
            }

    float* aw = ash + warp * 72;
    if (lane == 0) {
        #pragma unroll
        for (int j = 0; j < 4; j++)
            #pragma unroll
            for (int q = 0; q < 9; q++) {
                float lo, hi;
                unpack2(acc2[j][q], lo, hi);
                aw[j * 18 + 2 * q]     = lo;
                aw[j * 18 + 2 * q + 1] = hi;
            }
    }
    __syncwarp();

    for (int item = lane; item < 36; item += 32) {
        int j = item / 9;
        int p = item % 9;
        int ky = p / 3, kx = p % 3;
        float dy = aw[j * 18 + 2 * p]     + offset_b[2 * p];
        float dx = aw[j * 18 + 2 * p + 1] + offset_b[2 * p + 1];
        float py = dy + (float)ky + (float)(ho - 1);
        float px = dx + (float)kx + (float)(wo0 + j - 1);
        float y0f = floorf(py);
        float x0f = floorf(px);
        g_meta[((size_t)(n * PP + p)) * PIX_PER_N + ho * WO + wo0 + j] =
            make_float4(__int_as_float((int)y0f), __int_as_float((int)x0f),
                        py - y0f, px - x0f);
    }
}

// ---------------- kernel 4: gather + bf16 split mma GEMM + BN + SiLU ----------------
// 256 threads, tile = one ho row: 64 px x 128 co. 2 CTAs / SM.
// smem (bytes): BsH[0,34816) BsL[34816,69632) AsH[69632,87040) AsL[87040,104448)
//               msh[104448,113664) ssh[113664,+512) bsh[114176,+512)  total 114688
#define OFF_BSH 0
#define OFF_BSL 34816
#define OFF_ASH 69632
#define OFF_ASL 87040
#define OFF_MSH 104448
#define OFF_SSH 113664
#define OFF_BBH 114176
#define SMEM_MAIN 114688

// gather one pixel: lane covers 4 consecutive channels via LDG.128, packed f32x2 math
__device__ __forceinline__ void gather_px(int p, int pix, int lane,
                                          const float4* msh, const float* xn,
                                          char* AsH, char* AsL, ull NEG1) {
    float4 m = msh[p * 64 + pix];
    int y0 = __float_as_int(m.x);
    int x0 = __float_as_int(m.y);
    float wy = m.z, wx = m.w;
    ull w00 = bcast2((1.f - wy) * (1.f - wx));
    ull w01 = bcast2((1.f - wy) * wx);
    ull w10 = bcast2(wy * (1.f - wx));
    ull w11 = bcast2(wy * wx);
    bool vy0 = (unsigned)y0       < (unsigned)HH;
    bool vy1 = (unsigned)(y0 + 1) < (unsigned)HH;
    bool vx0 = (unsigned)x0       < (unsigned)WW;
    bool vx1 = (unsigned)(x0 + 1) < (unsigned)WW;
    const float* r0 = xn + (long long)y0 * (WW * CIN);
    const float* r1 = r0 + WW * CIN;
    int ch0 = lane * 4;
    float4 z = make_float4(0.f, 0.f, 0.f, 0.f);
    float4 c00 = (vy0 && vx0) ? *(const float4*)&r0[x0 * CIN + ch0]       : z;
    float4 c01 = (vy0 && vx1) ? *(const float4*)&r0[(x0 + 1) * CIN + ch0] : z;
    float4 c10 = (vy1 && vx0) ? *(const float4*)&r1[x0 * CIN + ch0]       : z;
    float4 c11 = (vy1 && vx1) ? *(const float4*)&r1[(x0 + 1) * CIN + ch0] : z;

    ull vA = 0ull, vB = 0ull;
    fma2(vA, w00, ((const ull*)&c00)[0]); fma2(vB, w00, ((const ull*)&c00)[1]);
    fma2(vA, w01, ((const ull*)&c01)[0]); fma2(vB, w01, ((const ull*)&c01)[1]);
    fma2(vA, w10, ((const ull*)&c10)[0]); fma2(vB, w10, ((const ull*)&c10)[1]);
    fma2(vA, w11, ((const ull*)&c11)[0]); fma2(vB, w11, ((const ull*)&c11)[1]);

    float a0, a1, b0, b1;
    unpack2(vA, a0, a1); unpack2(vB, b0, b1);
    u32 hA = cvt_bf16x2(a1, a0);
    u32 hB = cvt_bf16x2(b1, b0);
    // residual = v - f32(bf16_hi)
    ull hrA = pack2(__uint_as_float(hA << 16), __uint_as_float(hA & 0xffff0000u));
    ull hrB = pack2(__uint_as_float(hB << 16), __uint_as_float(hB & 0xffff0000u));
    fma2(vA, hrA, NEG1);
    fma2(vB, hrB, NEG1);
    unpack2(vA, a0, a1); unpack2(vB, b0, b1);
    u32 lA = cvt_bf16x2(a1, a0);
    u32 lB = cvt_bf16x2(b1, b0);

    int off = pix * ROWB + lane * 8;
    *(ull*)(AsH + off) = ((ull)hB << 32) | (ull)hA;
    *(ull*)(AsL + off) = ((ull)lB << 32) | (ull)lA;
}

__device__ __forceinline__ void gather_tap(int p, int gpix0, int lane,
                                           const float4* msh, const float* xn,
                                           char* AsH, char* AsL, ull NEG1) {
    #pragma unroll
    for (int pl = 0; pl < 8; pl++)
        gather_px(p, gpix0 + pl, lane, msh, xn, AsH, AsL, NEG1);
}

__device__ __forceinline__ void copy_bs(const __nv_bfloat16* src_g, u32 dst_u, int tid) {
    const char* src = (const char*)src_g;
    #pragma unroll
    for (int i = 0; i < 8; i++) {              // 2048 16B-chunks / 256 thr
        int c   = tid + i * 256;
        int row = c >> 4;
        int c16 = c & 15;
        cp_async16(dst_u + (u32)(row * ROWB + c16 * 16), src + row * 256 + c16 * 16);
    }
}

__global__ __launch_bounds__(256, 2)
void k_main(const float* __restrict__ gamma,
            const float* __restrict__ beta,
            const float* __restrict__ rmean,
            const float* __restrict__ rvar,
            float* __restrict__ out) {
    extern __shared__ char smc[];
    char*   AsH = smc + OFF_ASH;
    char*   AsL = smc + OFF_ASL;
    float4* msh = (float4*)(smc + OFF_MSH);
    float*  ssh = (float*)(smc + OFF_SSH);
    float*  bsh = (float*)(smc + OFF_BBH);
    u32 sbase = cvta_smem(smc);
    u32 bsHu = sbase + OFF_BSH, bsLu = sbase + OFF_BSL;
    u32 asHu = sbase + OFF_ASH, asLu = sbase + OFF_ASL;

    int tid  = threadIdx.x;
    int ho   = blockIdx.x;
    int n    = blockIdx.y;
    int lane = tid & 31;
    int warp = tid >> 5;
    int wm   = warp >> 2;          // 0..1 (32-pixel group)
    int wn   = warp & 3;           // 0..3 (32-cout group)
    int gpix0 = warp * 8;
    ull NEG1 = bcast2(-1.f);

    // stage metadata (64 px x 9 taps) + BN params
    for (int i = tid; i < PP * 64; i += 256) {
        int p   = i >> 6;
        int wo  = i & 63;
        msh[i] = g_meta[((size_t)(n * PP + p)) * PIX_PER_N + ho * WO + wo];
    }
    if (tid < COUT) {
        float s = gamma[tid] * rsqrtf(rvar[tid] + 1e-5f);
        ssh[tid] = s;
        bsh[tid] = beta[tid] - rmean[tid] * s;
    }
    __syncthreads();

    const float* xn = g_xT + (size_t)n * HW * CIN;

    // prologue: Bs(0) async + gather tap 0
    copy_bs(g_wh, bsHu, tid);
    copy_bs(g_wl, bsLu, tid);
    CP_COMMIT();
    gather_tap(0, gpix0, lane, msh, xn, AsH, AsL, NEG1);
    CP_WAIT(0);
    __syncthreads();

    float acc[2][4][4];
    #pragma unroll
    for (int mt = 0; mt < 2; mt++)
        #pragma unroll
        for (int nt = 0; nt < 4; nt++)
            #pragma unroll
            for (int i = 0; i < 4; i++) acc[mt][nt][i] = 0.f;

    int lrow = lane & 15;
    int lcol = (lane >> 4) << 4;

    for (int p = 0; p < PP; p++) {
        // ---- GEMM: 8 k-steps of 16, 3-term split ----
        #pragma unroll
        for (int ks = 0; ks < 8; ks++) {
            u32 k0b = (u32)(ks * 32 + lcol);
            u32 ah[2][4], al[2][4], bh[2][4], bl[2][4];
            #pragma unroll
            for (int mt = 0; mt < 2; mt++) {
                u32 ra = (u32)((wm * 32 + mt * 16 + lrow) * ROWB) + k0b;
                ldm4(ah[mt], asHu + ra);
                ldm4(al[mt], asLu + ra);
            }
            #pragma unroll
            for (int pr = 0; pr < 2; pr++) {
                u32 rb = (u32)((wn * 32 + pr * 16 + lrow) * ROWB) + k0b;
                ldm4(bh[pr], bsHu + rb);
                ldm4(bl[pr], bsLu + rb);
            }
            #pragma unroll
            for (int mt = 0; mt < 2; mt++)
                #pragma unroll
                for (int nt = 0; nt < 4; nt++) {
                    int pr = nt >> 1, s = nt & 1;
                    mma_bf16(acc[mt][nt], ah[mt], bh[pr][s], bh[pr][2 + s]);
                    mma_bf16(acc[mt][nt], ah[mt], bl[pr][s], bl[pr][2 + s]);
                    mma_bf16(acc[mt][nt], al[mt], bh[pr][s], bh[pr][2 + s]);
                }
        }
        __syncthreads();                  // done reading As/Bs for tap p
        if (p < PP - 1) {
            copy_bs(g_wh + (size_t)(p + 1) * COUT * CIN, bsHu, tid);
            copy_bs(g_wl + (size_t)(p + 1) * COUT * CIN, bsLu, tid);
            CP_COMMIT();
            gather_tap(p + 1, gpix0, lane, msh, xn, AsH, AsL, NEG1);
            CP_WAIT(0);
            __syncthreads();
        }
    }

    // ---- epilogue: BN + SiLU ----
    #pragma unroll
    for (int mt = 0; mt < 2; mt++)
        #pragma unroll
        for (int nt = 0; nt < 4; nt++) {
            int co = wn * 32 + nt * 8 + (lane & 3) * 2;
            int px = wm * 32 + mt * 16 + (lane >> 2);
            float s0 = ssh[co],     b0 = bsh[co];
            float s1 = ssh[co + 1], b1 = bsh[co + 1];
            #pragma unroll
            for (int h = 0; h < 2; h++) {
                int wo = px + h * 8;                 // 0..63
                float y0v = acc[mt][nt][h * 2 + 0] * s0 + b0;
                float y1v = acc[mt][nt][h * 2 + 1] * s1 + b1;
                out[(((size_t)(n * COUT + co))     * HO + ho) * WO + wo] = y0v / (1.f + expf(-y0v));
                out[(((size_t)(n * COUT + co + 1)) * HO + ho) * WO + wo] = y1v / (1.f + expf(-y1v));
            }
        }
}

// ---------------- launch ----------------
extern "C" void kernel_launch(void* const* d_in, const int* in_sizes, int n_in,
                              void* d_out, int out_size) {
    const float* x        = (const float*)d_in[0];
    const float* offset_w = (const float*)d_in[1];
    const float* offset_b = (const float*)d_in[2];
    const float* deform_w = (const float*)d_in[3];
    const float* gamma    = (const float*)d_in[4];
    const float* beta     = (const float*)d_in[5];
    const float* rmean    = (const float*)d_in[6];
    const float* rvar     = (const float*)d_in[7];
    float* out = (float*)d_out;

    cudaFuncSetAttribute(k_offset_meta, cudaFuncAttributeMaxDynamicSharedMemorySize, 90000);
    cudaFuncSetAttribute(k_main,        cudaFuncAttributeMaxDynamicSharedMemorySize, SMEM_MAIN);

    k_transpose_x<<<dim3(HW / 32, CIN / 32, NB), dim3(32, 8)>>>(x);
    k_prep_w<<<(PP * COUT * CIN + 255) / 256, 256>>>(deform_w);

    size_t sm3 = (size_t)(PP * 9 * CIN) * 8 + (size_t)(8 * 72) * 4;  // 85248 B
    k_offset_meta<<<NB * PIX_PER_N / 32, 256, sm3>>>(offset_w, offset_b);

    k_main<<<dim3(HO, NB), 256, SMEM_MAIN>>>(gamma, beta, rmean, rvar, out);
}

// round 8
// speedup vs baseline: 1.2893x; 1.0910x over previous
#include <cuda_runtime.h>
#include <cuda_bf16.h>
#include <math.h>

typedef unsigned long long ull;
typedef unsigned int u32;

// Problem constants
#define NB   16
#define CIN  128
#define COUT 128
#define HH   64
#define WW   64
#define HO   64
#define WO   64
#define PP   9
#define HW   (HH*WW)
#define PIX_PER_N (HO*WO)

#define ROWB 528   // smem row stride bytes (128 fp32 + 16B pad; r*528 % 128 = 16r -> conflict-free ldmatrix)

// ---------------- scratch ----------------
__device__ float  g_xT[NB * HH * WW * CIN];          // NHWC x (fp32)
__device__ float4 g_meta[NB * PP * HO * WO];         // y0,x0(bitcast),wy,wx
__device__ __align__(16) float g_wt[PP * COUT * CIN];// [p][cout][cin], tf32-rounded fp32

// ---------------- packed f32x2 helpers ----------------
__device__ __forceinline__ void fma2(ull& d, ull a, ull b) {
    asm("fma.rn.f32x2 %0, %1, %2, %0;" : "+l"(d) : "l"(a), "l"(b));
}
__device__ __forceinline__ void add2(ull& d, ull a, ull b) {
    asm("add.rn.f32x2 %0, %1, %2;" : "=l"(d) : "l"(a), "l"(b));
}
__device__ __forceinline__ ull bcast2(float a) {
    ull r; asm("mov.b64 %0, {%1, %1};" : "=l"(r) : "f"(a)); return r;
}
__device__ __forceinline__ ull pack2(float lo, float hi) {
    ull r; asm("mov.b64 %0, {%1, %2};" : "=l"(r) : "f"(lo), "f"(hi)); return r;
}
__device__ __forceinline__ void unpack2(ull v, float& lo, float& hi) {
    asm("mov.b64 {%0, %1}, %2;" : "=f"(lo), "=f"(hi) : "l"(v));
}
__device__ __forceinline__ u32 cvt_tf32(float f) {
    u32 r; asm("cvt.rna.tf32.f32 %0, %1;" : "=r"(r) : "f"(f)); return r;
}

// ---------------- mma helpers ----------------
__device__ __forceinline__ u32 cvta_smem(const void* p) {
    u32 r;
    asm("{ .reg .u64 t; cvta.to.shared.u64 t, %1; cvt.u32.u64 %0, t; }" : "=r"(r) : "l"(p));
    return r;
}
__device__ __forceinline__ void ldm4(u32* r, u32 addr) {
    asm volatile("ldmatrix.sync.aligned.m8n8.x4.shared.b16 {%0,%1,%2,%3}, [%4];"
                 : "=r"(r[0]), "=r"(r[1]), "=r"(r[2]), "=r"(r[3]) : "r"(addr));
}
__device__ __forceinline__ void mma_tf32(float* c, const u32* a, u32 b0, u32 b1) {
    asm volatile("mma.sync.aligned.m16n8k8.row.col.f32.tf32.tf32.f32 "
                 "{%0,%1,%2,%3}, {%4,%5,%6,%7}, {%8,%9}, {%0,%1,%2,%3};"
                 : "+f"(c[0]), "+f"(c[1]), "+f"(c[2]), "+f"(c[3])
                 : "r"(a[0]), "r"(a[1]), "r"(a[2]), "r"(a[3]), "r"(b0), "r"(b1));
}
__device__ __forceinline__ void cp_async16(u32 dst, const void* src) {
    asm volatile("cp.async.cg.shared.global [%0], [%1], 16;" :: "r"(dst), "l"(src));
}
#define CP_COMMIT()  asm volatile("cp.async.commit_group;" ::: "memory")
#define CP_WAIT(n)   asm volatile("cp.async.wait_group %0;" :: "n"(n) : "memory")

// ---------------- kernel 1: x NCHW -> NHWC ----------------
__global__ void k_transpose_x(const float* __restrict__ x) {
    __shared__ float tile[32][33];
    int n   = blockIdx.z;
    int hw0 = blockIdx.x * 32;
    int c0  = blockIdx.y * 32;
    int tx = threadIdx.x, ty = threadIdx.y;
    #pragma unroll
    for (int i = 0; i < 32; i += 8)
        tile[ty + i][tx] = x[((size_t)(n * CIN + c0 + ty + i)) * HW + hw0 + tx];
    __syncthreads();
    #pragma unroll
    for (int i = 0; i < 32; i += 8)
        g_xT[((size_t)(n * HW + hw0 + ty + i)) * CIN + c0 + tx] = tile[tx][ty + i];
}

// ---------------- kernel 2: deform_w -> tf32-rounded fp32 [p][cout][cin] ----------------
__global__ void k_prep_w(const float* __restrict__ w) {
    int i = blockIdx.x * 256 + threadIdx.x;
    if (i >= PP * COUT * CIN) return;
    int cin  = i & 127;
    int cout = (i >> 7) & 127;
    int p    = i >> 14;
    float v = w[(cout * CIN + cin) * PP + p];
    g_wt[i] = __uint_as_float(cvt_tf32(v));
}

// ---------------- kernel 3: offset conv (f32x2) + bilinear metadata ----------------
__global__ void k_offset_meta(const float* __restrict__ offset_w,
                              const float* __restrict__ offset_b) {
    extern __shared__ float sm_[];
    ull*   wsh2 = (ull*)sm_;                         // 9*9*128 ull
    float* ash  = sm_ + 2 * 9 * 9 * CIN;             // 8 warps * 72 floats

    int tid = threadIdx.x;
    for (int i = tid; i < PP * 9 * CIN; i += blockDim.x) {
        int cin = i & 127;
        int q   = (i >> 7) % 9;
        int p   = i / (9 * CIN);
        float lo = offset_w[((2 * q)     * CIN + cin) * PP + p];
        float hi = offset_w[((2 * q + 1) * CIN + cin) * PP + p];
        wsh2[i] = pack2(lo, hi);
    }
    __syncthreads();

    int lane = tid & 31;
    int warp = tid >> 5;
    int gw   = blockIdx.x * 8 + warp;
    int pb   = gw * 4;
    int n    = pb >> 12;
    int r    = pb & 4095;
    int ho   = r >> 6;
    int wo0  = r & 63;

    ull acc2[4][9];
    #pragma unroll
    for (int j = 0; j < 4; j++)
        #pragma unroll
        for (int q = 0; q < 9; q++) acc2[j][q] = 0ull;

    const float* xn = g_xT + (size_t)n * HW * CIN;

    #pragma unroll
    for (int p = 0; p < PP; p++) {
        int ky = p / 3, kx = p % 3;
        int ih = ho + ky - 1;
        bool vrow = (unsigned)ih < (unsigned)HH;
        #pragma unroll
        for (int cc = 0; cc < 4; cc++) {
            int cin = cc * 32 + lane;
            ull xb[4];
            #pragma unroll
            for (int j = 0; j < 4; j++) {
                int iw = wo0 + j + kx - 1;
                bool v = vrow && ((unsigned)iw < (unsigned)WW);
                float xv = v ? xn[((size_t)(ih * WW + iw)) * CIN + cin] : 0.f;
                xb[j] = bcast2(xv);
            }
            const ull* wrow = wsh2 + p * (9 * CIN) + cin;
            #pragma unroll
            for (int q = 0; q < 9; q++) {
                ull wq = wrow[q * CIN];
                fma2(acc2[0][q], xb[0], wq);
                fma2(acc2[1][q], xb[1], wq);
                fma2(acc2[2][q], xb[2], wq);
                fma2(acc2[3][q], xb[3], wq);
            }
        }
    }

    #pragma unroll
    for (int off = 16; off > 0; off >>= 1)
        #pragma unroll
        for (int j = 0; j < 4; j++)
            #pragma unroll
            for (int q = 0; q < 9; q++) {
                ull o = __shfl_down_sync(0xffffffffu, acc2[j][q], off);
                add2(acc2[j][q], acc2[j][q], o);
            }

    float* aw = ash + warp * 72;
    if (lane == 0) {
        #pragma unroll
        for (int j = 0; j < 4; j++)
            #pragma unroll
            for (int q = 0; q < 9; q++) {
                float lo, hi;
                unpack2(acc2[j][q], lo, hi);
                aw[j * 18 + 2 * q]     = lo;
                aw[j * 18 + 2 * q + 1] = hi;
            }
    }
    __syncwarp();

    for (int item = lane; item < 36; item += 32) {
        int j = item / 9;
        int p = item % 9;
        int ky = p / 3, kx = p % 3;
        float dy = aw[j * 18 + 2 * p]     + offset_b[2 * p];
        float dx = aw[j * 18 + 2 * p + 1] + offset_b[2 * p + 1];
        float py = dy + (float)ky + (float)(ho - 1);
        float px = dx + (float)kx + (float)(wo0 + j - 1);
        float y0f = floorf(py);
        float x0f = floorf(px);
        g_meta[((size_t)(n * PP + p)) * PIX_PER_N + ho * WO + wo0 + j] =
            make_float4(__int_as_float((int)y0f), __int_as_float((int)x0f),
                        py - y0f, px - x0f);
    }
}

// ---------------- kernel 4: gather + TF32 mma GEMM + BN + SiLU ----------------
// 256 threads, tile = one ho row: 64 px x 128 co. 2 CTAs/SM.
// smem (bytes): As[0,33792) Bs[33792,101376) msh[101376,110592)
//               ssh[110592,+512) bsh[111104,+512)  total 111616
#define OFF_AS  0
#define OFF_BS  33792
#define OFF_MSH 101376
#define OFF_SSH 110592
#define OFF_BBH 111104
#define SMEM_MAIN 111616

// gather one pixel: lane covers 4 channels via LDG.128; fp32 bilinear; tf32-round; STS.128
__device__ __forceinline__ void gather_px(int p, int pix, int lane,
                                          const float4* msh, const float* xn, char* smc) {
    float4 m = msh[p * 64 + pix];
    int y0 = __float_as_int(m.x);
    int x0 = __float_as_int(m.y);
    float wy = m.z, wx = m.w;
    ull w00 = bcast2((1.f - wy) * (1.f - wx));
    ull w01 = bcast2((1.f - wy) * wx);
    ull w10 = bcast2(wy * (1.f - wx));
    ull w11 = bcast2(wy * wx);
    bool vy0 = (unsigned)y0       < (unsigned)HH;
    bool vy1 = (unsigned)(y0 + 1) < (unsigned)HH;
    bool vx0 = (unsigned)x0       < (unsigned)WW;
    bool vx1 = (unsigned)(x0 + 1) < (unsigned)WW;
    const float* r0 = xn + (long long)y0 * (WW * CIN);
    const float* r1 = r0 + WW * CIN;
    int ch0 = lane * 4;
    float4 z = make_float4(0.f, 0.f, 0.f, 0.f);
    float4 c00 = (vy0 && vx0) ? *(const float4*)&r0[x0 * CIN + ch0]       : z;
    float4 c01 = (vy0 && vx1) ? *(const float4*)&r0[(x0 + 1) * CIN + ch0] : z;
    float4 c10 = (vy1 && vx0) ? *(const float4*)&r1[x0 * CIN + ch0]       : z;
    float4 c11 = (vy1 && vx1) ? *(const float4*)&r1[(x0 + 1) * CIN + ch0] : z;

    ull vA = 0ull, vB = 0ull;
    fma2(vA, w00, ((const ull*)&c00)[0]); fma2(vB, w00, ((const ull*)&c00)[1]);
    fma2(vA, w01, ((const ull*)&c01)[0]); fma2(vB, w01, ((const ull*)&c01)[1]);
    fma2(vA, w10, ((const ull*)&c10)[0]); fma2(vB, w10, ((const ull*)&c10)[1]);
    fma2(vA, w11, ((const ull*)&c11)[0]); fma2(vB, w11, ((const ull*)&c11)[1]);

    float a0, a1, b0, b1;
    unpack2(vA, a0, a1); unpack2(vB, b0, b1);
    uint4 t;
    t.x = cvt_tf32(a0); t.y = cvt_tf32(a1); t.z = cvt_tf32(b0); t.w = cvt_tf32(b1);
    *(uint4*)(smc + OFF_AS + pix * ROWB + ch0 * 4) = t;
}

__device__ __forceinline__ void copy_bs(const float* src_g, u32 dst_u, int tid) {
    const char* src = (const char*)src_g;
    #pragma unroll
    for (int i = 0; i < 16; i++) {           // 4096 16B-chunks / 256 thr
        int c   = tid + i * 256;
        int row = c >> 5;                    // 32 chunks per 512B row
        int c32 = c & 31;
        cp_async16(dst_u + (u32)(row * ROWB + c32 * 16), src + row * 512 + c32 * 16);
    }
}

__global__ __launch_bounds__(256, 2)
void k_main(const float* __restrict__ gamma,
            const float* __restrict__ beta,
            const float* __restrict__ rmean,
            const float* __restrict__ rvar,
            float* __restrict__ out) {
    extern __shared__ char smc[];
    float4* msh = (float4*)(smc + OFF_MSH);
    float*  ssh = (float*)(smc + OFF_SSH);
    float*  bsh = (float*)(smc + OFF_BBH);
    u32 sbase = cvta_smem(smc);
    u32 asU = sbase + OFF_AS;
    u32 bsU = sbase + OFF_BS;

    int tid  = threadIdx.x;
    int ho   = blockIdx.x;
    int n    = blockIdx.y;
    int lane = tid & 31;
    int warp = tid >> 5;
    int wm   = warp >> 2;          // 0..1 (32-pixel group)
    int wn   = warp & 3;           // 0..3 (32-cout group)
    int gpix0 = warp * 8;

    // stage metadata + BN params
    for (int i = tid; i < PP * 64; i += 256) {
        int p  = i >> 6;
        int wo = i & 63;
        msh[i] = g_meta[((size_t)(n * PP + p)) * PIX_PER_N + ho * WO + wo];
    }
    if (tid < COUT) {
        float s = gamma[tid] * rsqrtf(rvar[tid] + 1e-5f);
        ssh[tid] = s;
        bsh[tid] = beta[tid] - rmean[tid] * s;
    }
    __syncthreads();

    const float* xn = g_xT + (size_t)n * HW * CIN;

    // prologue: Bs(0) async + gather tap 0
    copy_bs(g_wt, bsU, tid);
    CP_COMMIT();
    #pragma unroll 4
    for (int pl = 0; pl < 8; pl++)
        gather_px(0, gpix0 + pl, lane, msh, xn, smc);
    CP_WAIT(0);
    __syncthreads();

    float acc[2][4][4];
    #pragma unroll
    for (int mt = 0; mt < 2; mt++)
        #pragma unroll
        for (int nt = 0; nt < 4; nt++)
            #pragma unroll
            for (int i = 0; i < 4; i++) acc[mt][nt][i] = 0.f;

    // ldmatrix lane addressing: rows (lane&7) + bit3*8, byte col + (lane>>4)*16
    int rsub = (lane & 7) + ((lane >> 3) & 1) * 8;
    u32 ccol = (u32)((lane >> 4) << 4);
    u32 aRow0 = asU + (u32)((wm * 32 + rsub) * ROWB) + ccol;   // m-tile 0
    u32 bRow0 = bsU + (u32)((wn * 32 + rsub) * ROWB) + ccol;   // n-tiles 0,1

    for (int p = 0; p < PP; p++) {
        // ---- GEMM: 16 k8-steps, single-pass tf32 ----
        #pragma unroll
        for (int ks = 0; ks < 16; ks++) {
            u32 kb = (u32)(ks * 32);
            u32 a[2][4], b[2][4];
            ldm4(a[0], aRow0 + kb);
            ldm4(a[1], aRow0 + kb + 16u * ROWB);
            ldm4(b[0], bRow0 + kb);
            ldm4(b[1], bRow0 + kb + 16u * ROWB);
            #pragma unroll
            for (int mt = 0; mt < 2; mt++)
                #pragma unroll
                for (int nt = 0; nt < 4; nt++) {
                    int bt = nt >> 1, s = nt & 1;
                    mma_tf32(acc[mt][nt], a[mt], b[bt][s], b[bt][2 + s]);
                }
        }
        __syncthreads();                  // done reading As/Bs for tap p
        if (p < PP - 1) {
            copy_bs(g_wt + (size_t)(p + 1) * COUT * CIN, bsU, tid);
            CP_COMMIT();
            #pragma unroll 4
            for (int pl = 0; pl < 8; pl++)
                gather_px(p + 1, gpix0 + pl, lane, msh, xn, smc);
            CP_WAIT(0);
            __syncthreads();
        }
    }

    // ---- epilogue: BN + SiLU (fast sigmoid) ----
    #pragma unroll
    for (int mt = 0; mt < 2; mt++)
        #pragma unroll
        for (int nt = 0; nt < 4; nt++) {
            int co = wn * 32 + nt * 8 + (lane & 3) * 2;
            int px = wm * 32 + mt * 16 + (lane >> 2);
            float s0 = ssh[co],     b0 = bsh[co];
            float s1 = ssh[co + 1], b1 = bsh[co + 1];
            #pragma unroll
            for (int h = 0; h < 2; h++) {
                int wo = px + h * 8;                 // 0..63
                float y0v = acc[mt][nt][h * 2 + 0] * s0 + b0;
                float y1v = acc[mt][nt][h * 2 + 1] * s1 + b1;
                out[(((size_t)(n * COUT + co))     * HO + ho) * WO + wo] = y0v / (1.f + __expf(-y0v));
                out[(((size_t)(n * COUT + co + 1)) * HO + ho) * WO + wo] = y1v / (1.f + __expf(-y1v));
            }
        }
}

// ---------------- launch ----------------
extern "C" void kernel_launch(void* const* d_in, const int* in_sizes, int n_in,
                              void* d_out, int out_size) {
    const float* x        = (const float*)d_in[0];
    const float* offset_w = (const float*)d_in[1];
    const float* offset_b = (const float*)d_in[2];
    const float* deform_w = (const float*)d_in[3];
    const float* gamma    = (const float*)d_in[4];
    const float* beta     = (const float*)d_in[5];
    const float* rmean    = (const float*)d_in[6];
    const float* rvar     = (const float*)d_in[7];
    float* out = (float*)d_out;

    cudaFuncSetAttribute(k_offset_meta, cudaFuncAttributeMaxDynamicSharedMemorySize, 90000);
    cudaFuncSetAttribute(k_main,        cudaFuncAttributeMaxDynamicSharedMemorySize, SMEM_MAIN);

    k_transpose_x<<<dim3(HW / 32, CIN / 32, NB), dim3(32, 8)>>>(x);
    k_prep_w<<<(PP * COUT * CIN + 255) / 256, 256>>>(deform_w);

    size_t sm3 = (size_t)(PP * 9 * CIN) * 8 + (size_t)(8 * 72) * 4;  // 85248 B
    k_offset_meta<<<NB * PIX_PER_N / 32, 256, sm3>>>(offset_w, offset_b);

    k_main<<<dim3(HO, NB), 256, SMEM_MAIN>>>(gamma, beta, rmean, rvar, out);
}

// round 9
// speedup vs baseline: 1.5604x; 1.2103x over previous
#include <cuda_runtime.h>
#include <cuda_bf16.h>
#include <cuda_fp16.h>
#include <math.h>

typedef unsigned long long ull;
typedef unsigned int u32;

// Problem constants
#define NB   16
#define CIN  128
#define COUT 128
#define HH   64
#define WW   64
#define HO   64
#define WO   64
#define PP   9
#define HW   (HH*WW)
#define PIX_PER_N (HO*WO)

#define ROWB 272   // smem row stride (136 f16 = 17*16B, conflict-free ldmatrix)

// ---------------- scratch ----------------
__device__ float  g_xT[NB * HH * WW * CIN];          // NHWC x (fp32)
__device__ float4 g_meta[NB * PP * HO * WO];         // y0,x0(bitcast),wy,wx
__device__ __align__(16) __half g_wf[PP * COUT * CIN]; // [p][cout][cin] fp16

// ---------------- packed f32x2 helpers ----------------
__device__ __forceinline__ void fma2(ull& d, ull a, ull b) {
    asm("fma.rn.f32x2 %0, %1, %2, %0;" : "+l"(d) : "l"(a), "l"(b));
}
__device__ __forceinline__ void add2(ull& d, ull a, ull b) {
    asm("add.rn.f32x2 %0, %1, %2;" : "=l"(d) : "l"(a), "l"(b));
}
__device__ __forceinline__ ull bcast2(float a) {
    ull r; asm("mov.b64 %0, {%1, %1};" : "=l"(r) : "f"(a)); return r;
}
__device__ __forceinline__ ull pack2(float lo, float hi) {
    ull r; asm("mov.b64 %0, {%1, %2};" : "=l"(r) : "f"(lo), "f"(hi)); return r;
}
__device__ __forceinline__ void unpack2(ull v, float& lo, float& hi) {
    asm("mov.b64 {%0, %1}, %2;" : "=f"(lo), "=f"(hi) : "l"(v));
}
__device__ __forceinline__ u32 cvt_f16x2(float hi, float lo) {   // hi->upper half
    u32 r; asm("cvt.rn.f16x2.f32 %0, %1, %2;" : "=r"(r) : "f"(hi), "f"(lo)); return r;
}

// ---------------- mma helpers ----------------
__device__ __forceinline__ u32 cvta_smem(const void* p) {
    u32 r;
    asm("{ .reg .u64 t; cvta.to.shared.u64 t, %1; cvt.u32.u64 %0, t; }" : "=r"(r) : "l"(p));
    return r;
}
__device__ __forceinline__ void ldm4(u32* r, u32 addr) {
    asm volatile("ldmatrix.sync.aligned.m8n8.x4.shared.b16 {%0,%1,%2,%3}, [%4];"
                 : "=r"(r[0]), "=r"(r[1]), "=r"(r[2]), "=r"(r[3]) : "r"(addr));
}
__device__ __forceinline__ void mma_f16(float* c, const u32* a, u32 b0, u32 b1) {
    asm volatile("mma.sync.aligned.m16n8k16.row.col.f32.f16.f16.f32 "
                 "{%0,%1,%2,%3}, {%4,%5,%6,%7}, {%8,%9}, {%0,%1,%2,%3};"
                 : "+f"(c[0]), "+f"(c[1]), "+f"(c[2]), "+f"(c[3])
                 : "r"(a[0]), "r"(a[1]), "r"(a[2]), "r"(a[3]), "r"(b0), "r"(b1));
}
__device__ __forceinline__ void cp_async16(u32 dst, const void* src) {
    asm volatile("cp.async.cg.shared.global [%0], [%1], 16;" :: "r"(dst), "l"(src));
}
#define CP_COMMIT()  asm volatile("cp.async.commit_group;" ::: "memory")
#define CP_WAIT(n)   asm volatile("cp.async.wait_group %0;" :: "n"(n) : "memory")

// ---------------- kernel 1: x NCHW -> NHWC ----------------
__global__ void k_transpose_x(const float* __restrict__ x) {
    __shared__ float tile[32][33];
    int n   = blockIdx.z;
    int hw0 = blockIdx.x * 32;
    int c0  = blockIdx.y * 32;
    int tx = threadIdx.x, ty = threadIdx.y;
    #pragma unroll
    for (int i = 0; i < 32; i += 8)
        tile[ty + i][tx] = x[((size_t)(n * CIN + c0 + ty + i)) * HW + hw0 + tx];
    __syncthreads();
    #pragma unroll
    for (int i = 0; i < 32; i += 8)
        g_xT[((size_t)(n * HW + hw0 + ty + i)) * CIN + c0 + tx] = tile[tx][ty + i];
}

// ---------------- kernel 2: deform_w -> fp16 [p][cout][cin] ----------------
__global__ void k_prep_w(const float* __restrict__ w) {
    int i = blockIdx.x * 256 + threadIdx.x;
    if (i >= PP * COUT * CIN) return;
    int cin  = i & 127;
    int cout = (i >> 7) & 127;
    int p    = i >> 14;
    g_wf[i] = __float2half_rn(w[(cout * CIN + cin) * PP + p]);
}

// ---------------- kernel 3: offset conv (f32x2) + bilinear metadata ----------------
__global__ void k_offset_meta(const float* __restrict__ offset_w,
                              const float* __restrict__ offset_b) {
    extern __shared__ float sm_[];
    ull*   wsh2 = (ull*)sm_;                         // 9*9*128 ull
    float* ash  = sm_ + 2 * 9 * 9 * CIN;             // 8 warps * 72 floats

    int tid = threadIdx.x;
    for (int i = tid; i < PP * 9 * CIN; i += blockDim.x) {
        int cin = i & 127;
        int q   = (i >> 7) % 9;
        int p   = i / (9 * CIN);
        float lo = offset_w[((2 * q)     * CIN + cin) * PP + p];
        float hi = offset_w[((2 * q + 1) * CIN + cin) * PP + p];
        wsh2[i] = pack2(lo, hi);
    }
    __syncthreads();

    int lane = tid & 31;
    int warp = tid >> 5;
    int gw   = blockIdx.x * 8 + warp;
    int pb   = gw * 4;
    int n    = pb >> 12;
    int r    = pb & 4095;
    int ho   = r >> 6;
    int wo0  = r & 63;

    ull acc2[4][9];
    #pragma unroll
    for (int j = 0; j < 4; j++)
        #pragma unroll
        for (int q = 0; q < 9; q++) acc2[j][q] = 0ull;

    const float* xn = g_xT + (size_t)n * HW * CIN;

    #pragma unroll
    for (int p = 0; p < PP; p++) {
        int ky = p / 3, kx = p % 3;
        int ih = ho + ky - 1;
        bool vrow = (unsigned)ih < (unsigned)HH;
        #pragma unroll
        for (int cc = 0; cc < 4; cc++) {
            int cin = cc * 32 + lane;
            ull xb[4];
            #pragma unroll
            for (int j = 0; j < 4; j++) {
                int iw = wo0 + j + kx - 1;
                bool v = vrow && ((unsigned)iw < (unsigned)WW);
                float xv = v ? xn[((size_t)(ih * WW + iw)) * CIN + cin] : 0.f;
                xb[j] = bcast2(xv);
            }
            const ull* wrow = wsh2 + p * (9 * CIN) + cin;
            #pragma unroll
            for (int q = 0; q < 9; q++) {
                ull wq = wrow[q * CIN];
                fma2(acc2[0][q], xb[0], wq);
                fma2(acc2[1][q], xb[1], wq);
                fma2(acc2[2][q], xb[2], wq);
                fma2(acc2[3][q], xb[3], wq);
            }
        }
    }

    #pragma unroll
    for (int off = 16; off > 0; off >>= 1)
        #pragma unroll
        for (int j = 0; j < 4; j++)
            #pragma unroll
            for (int q = 0; q < 9; q++) {
                ull o = __shfl_down_sync(0xffffffffu, acc2[j][q], off);
                add2(acc2[j][q], acc2[j][q], o);
            }

    float* aw = ash + warp * 72;
    if (lane == 0) {
        #pragma unroll
        for (int j = 0; j < 4; j++)
            #pragma unroll
            for (int q = 0; q < 9; q++) {
                float lo, hi;
                unpack2(acc2[j][q], lo, hi);
                aw[j * 18 + 2 * q]     = lo;
                aw[j * 18 + 2 * q + 1] = hi;
            }
    }
    __syncwarp();

    for (int item = lane; item < 36; item += 32) {
        int j = item / 9;
        int p = item % 9;
        int ky = p / 3, kx = p % 3;
        float dy = aw[j * 18 + 2 * p]     + offset_b[2 * p];
        float dx = aw[j * 18 + 2 * p + 1] + offset_b[2 * p + 1];
        float py = dy + (float)ky + (float)(ho - 1);
        float px = dx + (float)kx + (float)(wo0 + j - 1);
        float y0f = floorf(py);
        float x0f = floorf(px);
        g_meta[((size_t)(n * PP + p)) * PIX_PER_N + ho * WO + wo0 + j] =
            make_float4(__int_as_float((int)y0f), __int_as_float((int)x0f),
                        py - y0f, px - x0f);
    }
}

// ---------------- kernel 4: gather + fp16 mma GEMM + BN + SiLU ----------------
// 256 threads, tile = one ho row: 64 px x 128 co. 3 CTAs/SM.
// smem (bytes): As[0,17408) Bs[17408,52224) msh[52224,61440)
//               ssh[61440,+512) bsh[61952,+512)  total 62464
#define OFF_AS  0
#define OFF_BS  17408
#define OFF_MSH 52224
#define OFF_SSH 61440
#define OFF_BBH 61952
#define SMEM_MAIN 62464

// gather one pixel: lane covers 4 channels via LDG.128; fp32 bilinear (f32x2); f16x2 STS.64
__device__ __forceinline__ void gather_px(int p, int pix, int lane,
                                          const float4* msh, const float* xn, char* smc) {
    float4 m = msh[p * 64 + pix];
    int y0 = __float_as_int(m.x);
    int x0 = __float_as_int(m.y);
    float wy = m.z, wx = m.w;
    ull w00 = bcast2((1.f - wy) * (1.f - wx));
    ull w01 = bcast2((1.f - wy) * wx);
    ull w10 = bcast2(wy * (1.f - wx));
    ull w11 = bcast2(wy * wx);
    bool vy0 = (unsigned)y0       < (unsigned)HH;
    bool vy1 = (unsigned)(y0 + 1) < (unsigned)HH;
    bool vx0 = (unsigned)x0       < (unsigned)WW;
    bool vx1 = (unsigned)(x0 + 1) < (unsigned)WW;
    const float* r0 = xn + (long long)y0 * (WW * CIN);
    const float* r1 = r0 + WW * CIN;
    int ch0 = lane * 4;
    float4 z = make_float4(0.f, 0.f, 0.f, 0.f);
    float4 c00 = (vy0 && vx0) ? *(const float4*)&r0[x0 * CIN + ch0]       : z;
    float4 c01 = (vy0 && vx1) ? *(const float4*)&r0[(x0 + 1) * CIN + ch0] : z;
    float4 c10 = (vy1 && vx0) ? *(const float4*)&r1[x0 * CIN + ch0]       : z;
    float4 c11 = (vy1 && vx1) ? *(const float4*)&r1[(x0 + 1) * CIN + ch0] : z;

    ull vA = 0ull, vB = 0ull;
    fma2(vA, w00, ((const ull*)&c00)[0]); fma2(vB, w00, ((const ull*)&c00)[1]);
    fma2(vA, w01, ((const ull*)&c01)[0]); fma2(vB, w01, ((const ull*)&c01)[1]);
    fma2(vA, w10, ((const ull*)&c10)[0]); fma2(vB, w10, ((const ull*)&c10)[1]);
    fma2(vA, w11, ((const ull*)&c11)[0]); fma2(vB, w11, ((const ull*)&c11)[1]);

    float a0, a1, b0, b1;
    unpack2(vA, a0, a1); unpack2(vB, b0, b1);
    u32 lo_pair = cvt_f16x2(a1, a0);     // ch0 in lower half, ch1 upper
    u32 hi_pair = cvt_f16x2(b1, b0);     // ch2 lower, ch3 upper
    *(ull*)(smc + OFF_AS + pix * ROWB + ch0 * 2) = ((ull)hi_pair << 32) | (ull)lo_pair;
}

__device__ __forceinline__ void copy_bs(const __half* src_g, u32 dst_u, int tid) {
    const char* src = (const char*)src_g;
    #pragma unroll
    for (int i = 0; i < 8; i++) {            // 2048 16B-chunks / 256 thr
        int c   = tid + i * 256;
        int row = c >> 4;                    // cout row (256B per row)
        int c16 = c & 15;
        cp_async16(dst_u + (u32)(row * ROWB + c16 * 16), src + row * 256 + c16 * 16);
    }
}

__global__ __launch_bounds__(256, 3)
void k_main(const float* __restrict__ gamma,
            const float* __restrict__ beta,
            const float* __restrict__ rmean,
            const float* __restrict__ rvar,
            float* __restrict__ out) {
    extern __shared__ char smc[];
    float4* msh = (float4*)(smc + OFF_MSH);
    float*  ssh = (float*)(smc + OFF_SSH);
    float*  bsh = (float*)(smc + OFF_BBH);
    u32 sbase = cvta_smem(smc);
    u32 asU = sbase + OFF_AS;
    u32 bsU = sbase + OFF_BS;

    int tid  = threadIdx.x;
    int ho   = blockIdx.x;
    int n    = blockIdx.y;
    int lane = tid & 31;
    int warp = tid >> 5;
    int wm   = warp >> 2;          // 0..1 (32-pixel group)
    int wn   = warp & 3;           // 0..3 (32-cout group)
    int gpix0 = warp * 8;

    // stage metadata + BN params
    for (int i = tid; i < PP * 64; i += 256) {
        int p  = i >> 6;
        int wo = i & 63;
        msh[i] = g_meta[((size_t)(n * PP + p)) * PIX_PER_N + ho * WO + wo];
    }
    if (tid < COUT) {
        float s = gamma[tid] * rsqrtf(rvar[tid] + 1e-5f);
        ssh[tid] = s;
        bsh[tid] = beta[tid] - rmean[tid] * s;
    }
    __syncthreads();

    const float* xn = g_xT + (size_t)n * HW * CIN;

    // prologue: Bs(0) async + gather tap 0
    copy_bs(g_wf, bsU, tid);
    CP_COMMIT();
    #pragma unroll 4
    for (int pl = 0; pl < 8; pl++)
        gather_px(0, gpix0 + pl, lane, msh, xn, smc);
    CP_WAIT(0);
    __syncthreads();

    float acc[2][4][4];
    #pragma unroll
    for (int mt = 0; mt < 2; mt++)
        #pragma unroll
        for (int nt = 0; nt < 4; nt++)
            #pragma unroll
            for (int i = 0; i < 4; i++) acc[mt][nt][i] = 0.f;

    int lrow = lane & 15;
    int lcol = (lane >> 4) << 4;

    for (int p = 0; p < PP; p++) {
        // ---- GEMM: 8 k16-steps, single-pass fp16 ----
        #pragma unroll
        for (int ks = 0; ks < 8; ks++) {
            u32 k0b = (u32)(ks * 32 + lcol);
            u32 a[2][4], b[2][4];
            #pragma unroll
            for (int mt = 0; mt < 2; mt++)
                ldm4(a[mt], asU + (u32)((wm * 32 + mt * 16 + lrow) * ROWB) + k0b);
            #pragma unroll
            for (int pr = 0; pr < 2; pr++)
                ldm4(b[pr], bsU + (u32)((wn * 32 + pr * 16 + lrow) * ROWB) + k0b);
            #pragma unroll
            for (int mt = 0; mt < 2; mt++)
                #pragma unroll
                for (int nt = 0; nt < 4; nt++) {
                    int pr = nt >> 1, s = nt & 1;
                    mma_f16(acc[mt][nt], a[mt], b[pr][s], b[pr][2 + s]);
                }
        }
        __syncthreads();                  // done reading As/Bs for tap p
        if (p < PP - 1) {
            copy_bs(g_wf + (size_t)(p + 1) * COUT * CIN, bsU, tid);
            CP_COMMIT();
            #pragma unroll 4
            for (int pl = 0; pl < 8; pl++)
                gather_px(p + 1, gpix0 + pl, lane, msh, xn, smc);
            CP_WAIT(0);
            __syncthreads();
        }
    }

    // ---- epilogue: BN + SiLU (fast sigmoid) ----
    #pragma unroll
    for (int mt = 0; mt < 2; mt++)
        #pragma unroll
        for (int nt = 0; nt < 4; nt++) {
            int co = wn * 32 + nt * 8 + (lane & 3) * 2;
            int px = wm * 32 + mt * 16 + (lane >> 2);
            float s0 = ssh[co],     b0 = bsh[co];
            float s1 = ssh[co + 1], b1 = bsh[co + 1];
            #pragma unroll
            for (int h = 0; h < 2; h++) {
                int wo = px + h * 8;                 // 0..63
                float y0v = acc[mt][nt][h * 2 + 0] * s0 + b0;
                float y1v = acc[mt][nt][h * 2 + 1] * s1 + b1;
                out[(((size_t)(n * COUT + co))     * HO + ho) * WO + wo] = y0v / (1.f + __expf(-y0v));
                out[(((size_t)(n * COUT + co + 1)) * HO + ho) * WO + wo] = y1v / (1.f + __expf(-y1v));
            }
        }
}

// ---------------- launch ----------------
extern "C" void kernel_launch(void* const* d_in, const int* in_sizes, int n_in,
                              void* d_out, int out_size) {
    const float* x        = (const float*)d_in[0];
    const float* offset_w = (const float*)d_in[1];
    const float* offset_b = (const float*)d_in[2];
    const float* deform_w = (const float*)d_in[3];
    const float* gamma    = (const float*)d_in[4];
    const float* beta     = (const float*)d_in[5];
    const float* rmean    = (const float*)d_in[6];
    const float* rvar     = (const float*)d_in[7];
    float* out = (float*)d_out;

    cudaFuncSetAttribute(k_offset_meta, cudaFuncAttributeMaxDynamicSharedMemorySize, 90000);
    cudaFuncSetAttribute(k_main,        cudaFuncAttributeMaxDynamicSharedMemorySize, SMEM_MAIN);

    k_transpose_x<<<dim3(HW / 32, CIN / 32, NB), dim3(32, 8)>>>(x);
    k_prep_w<<<(PP * COUT * CIN + 255) / 256, 256>>>(deform_w);

    size_t sm3 = (size_t)(PP * 9 * CIN) * 8 + (size_t)(8 * 72) * 4;  // 85248 B
    k_offset_meta<<<NB * PIX_PER_N / 32, 256, sm3>>>(offset_w, offset_b);

    k_main<<<dim3(HO, NB), 256, SMEM_MAIN>>>(gamma, beta, rmean, rvar, out);
}

// round 10
// speedup vs baseline: 1.7547x; 1.1245x over previous
#include <cuda_runtime.h>
#include <cuda_bf16.h>
#include <cuda_fp16.h>
#include <math.h>

typedef unsigned long long ull;
typedef unsigned int u32;

// Problem constants
#define NB   16
#define CIN  128
#define COUT 128
#define HH   64
#define WW   64
#define HO   64
#define WO   64
#define PP   9
#define HW   (HH*WW)
#define PIX_PER_N (HO*WO)

#define ROWB 272   // smem row stride (136 f16 = 17*16B, conflict-free ldmatrix)

// ---------------- scratch ----------------
__device__ __align__(16) __half g_xh[NB * HH * WW * CIN];  // NHWC x, fp16 (16.7MB)
__device__ float4 g_meta[NB * PP * HO * WO];               // y0,x0(bitcast),wy,wx
__device__ __align__(16) __half g_wf[PP * COUT * CIN];     // [p][cout][cin] fp16

// ---------------- packed f32x2 helpers ----------------
__device__ __forceinline__ void fma2(ull& d, ull a, ull b) {
    asm("fma.rn.f32x2 %0, %1, %2, %0;" : "+l"(d) : "l"(a), "l"(b));
}
__device__ __forceinline__ void add2(ull& d, ull a, ull b) {
    asm("add.rn.f32x2 %0, %1, %2;" : "=l"(d) : "l"(a), "l"(b));
}
__device__ __forceinline__ ull bcast2(float a) {
    ull r; asm("mov.b64 %0, {%1, %1};" : "=l"(r) : "f"(a)); return r;
}
__device__ __forceinline__ ull pack2(float lo, float hi) {
    ull r; asm("mov.b64 %0, {%1, %2};" : "=l"(r) : "f"(lo), "f"(hi)); return r;
}
__device__ __forceinline__ void unpack2(ull v, float& lo, float& hi) {
    asm("mov.b64 {%0, %1}, %2;" : "=f"(lo), "=f"(hi) : "l"(v));
}

// ---------------- mma helpers ----------------
__device__ __forceinline__ u32 cvta_smem(const void* p) {
    u32 r;
    asm("{ .reg .u64 t; cvta.to.shared.u64 t, %1; cvt.u32.u64 %0, t; }" : "=r"(r) : "l"(p));
    return r;
}
__device__ __forceinline__ void ldm4(u32* r, u32 addr) {
    asm volatile("ldmatrix.sync.aligned.m8n8.x4.shared.b16 {%0,%1,%2,%3}, [%4];"
                 : "=r"(r[0]), "=r"(r[1]), "=r"(r[2]), "=r"(r[3]) : "r"(addr));
}
__device__ __forceinline__ void mma_f16(float* c, const u32* a, u32 b0, u32 b1) {
    asm volatile("mma.sync.aligned.m16n8k16.row.col.f32.f16.f16.f32 "
                 "{%0,%1,%2,%3}, {%4,%5,%6,%7}, {%8,%9}, {%0,%1,%2,%3};"
                 : "+f"(c[0]), "+f"(c[1]), "+f"(c[2]), "+f"(c[3])
                 : "r"(a[0]), "r"(a[1]), "r"(a[2]), "r"(a[3]), "r"(b0), "r"(b1));
}
__device__ __forceinline__ void cp_async16(u32 dst, const void* src) {
    asm volatile("cp.async.cg.shared.global [%0], [%1], 16;" :: "r"(dst), "l"(src));
}
#define CP_COMMIT()  asm volatile("cp.async.commit_group;" ::: "memory")
#define CP_WAIT(n)   asm volatile("cp.async.wait_group %0;" :: "n"(n) : "memory")

// ---------------- kernel 1: x NCHW fp32 -> NHWC fp16 ----------------
__global__ void k_transpose_x(const float* __restrict__ x) {
    __shared__ float tile[32][33];
    int n   = blockIdx.z;
    int hw0 = blockIdx.x * 32;
    int c0  = blockIdx.y * 32;
    int tx = threadIdx.x, ty = threadIdx.y;
    #pragma unroll
    for (int i = 0; i < 32; i += 8)
        tile[ty + i][tx] = x[((size_t)(n * CIN + c0 + ty + i)) * HW + hw0 + tx];
    __syncthreads();
    #pragma unroll
    for (int i = 0; i < 32; i += 8)
        g_xh[((size_t)(n * HW + hw0 + ty + i)) * CIN + c0 + tx] =
            __float2half_rn(tile[tx][ty + i]);
}

// ---------------- kernel 2: deform_w -> fp16 [p][cout][cin] ----------------
__global__ void k_prep_w(const float* __restrict__ w) {
    int i = blockIdx.x * 256 + threadIdx.x;
    if (i >= PP * COUT * CIN) return;
    int cin  = i & 127;
    int cout = (i >> 7) & 127;
    int p    = i >> 14;
    g_wf[i] = __float2half_rn(w[(cout * CIN + cin) * PP + p]);
}

// ---------------- kernel 3: offset conv (f32x2, fp16 x) + bilinear metadata --------
__global__ void k_offset_meta(const float* __restrict__ offset_w,
                              const float* __restrict__ offset_b) {
    extern __shared__ float sm_[];
    ull*   wsh2 = (ull*)sm_;                         // 9*9*128 ull
    float* ash  = sm_ + 2 * 9 * 9 * CIN;             // 8 warps * 72 floats

    int tid = threadIdx.x;
    for (int i = tid; i < PP * 9 * CIN; i += blockDim.x) {
        int cin = i & 127;
        int q   = (i >> 7) % 9;
        int p   = i / (9 * CIN);
        float lo = offset_w[((2 * q)     * CIN + cin) * PP + p];
        float hi = offset_w[((2 * q + 1) * CIN + cin) * PP + p];
        wsh2[i] = pack2(lo, hi);
    }
    __syncthreads();

    int lane = tid & 31;
    int warp = tid >> 5;
    int gw   = blockIdx.x * 8 + warp;
    int pb   = gw * 4;
    int n    = pb >> 12;
    int r    = pb & 4095;
    int ho   = r >> 6;
    int wo0  = r & 63;

    ull acc2[4][9];
    #pragma unroll
    for (int j = 0; j < 4; j++)
        #pragma unroll
        for (int q = 0; q < 9; q++) acc2[j][q] = 0ull;

    const __half* xn = g_xh + (size_t)n * HW * CIN;

    #pragma unroll
    for (int p = 0; p < PP; p++) {
        int ky = p / 3, kx = p % 3;
        int ih = ho + ky - 1;
        bool vrow = (unsigned)ih < (unsigned)HH;
        #pragma unroll
        for (int cc = 0; cc < 4; cc++) {
            int cin = cc * 32 + lane;
            ull xb[4];
            #pragma unroll
            for (int j = 0; j < 4; j++) {
                int iw = wo0 + j + kx - 1;
                bool v = vrow && ((unsigned)iw < (unsigned)WW);
                float xv = v ? __half2float(xn[((size_t)(ih * WW + iw)) * CIN + cin]) : 0.f;
                xb[j] = bcast2(xv);
            }
            const ull* wrow = wsh2 + p * (9 * CIN) + cin;
            #pragma unroll
            for (int q = 0; q < 9; q++) {
                ull wq = wrow[q * CIN];
                fma2(acc2[0][q], xb[0], wq);
                fma2(acc2[1][q], xb[1], wq);
                fma2(acc2[2][q], xb[2], wq);
                fma2(acc2[3][q], xb[3], wq);
            }
        }
    }

    #pragma unroll
    for (int off = 16; off > 0; off >>= 1)
        #pragma unroll
        for (int j = 0; j < 4; j++)
            #pragma unroll
            for (int q = 0; q < 9; q++) {
                ull o = __shfl_down_sync(0xffffffffu, acc2[j][q], off);
                add2(acc2[j][q], acc2[j][q], o);
            }

    float* aw = ash + warp * 72;
    if (lane == 0) {
        #pragma unroll
        for (int j = 0; j < 4; j++)
            #pragma unroll
            for (int q = 0; q < 9; q++) {
                float lo, hi;
                unpack2(acc2[j][q], lo, hi);
                aw[j * 18 + 2 * q]     = lo;
                aw[j * 18 + 2 * q + 1] = hi;
            }
    }
    __syncwarp();

    for (int item = lane; item < 36; item += 32) {
        int j = item / 9;
        int p = item % 9;
        int ky = p / 3, kx = p % 3;
        float dy = aw[j * 18 + 2 * p]     + offset_b[2 * p];
        float dx = aw[j * 18 + 2 * p + 1] + offset_b[2 * p + 1];
        float py = dy + (float)ky + (float)(ho - 1);
        float px = dx + (float)kx + (float)(wo0 + j - 1);
        float y0f = floorf(py);
        float x0f = floorf(px);
        g_meta[((size_t)(n * PP + p)) * PIX_PER_N + ho * WO + wo0 + j] =
            make_float4(__int_as_float((int)y0f), __int_as_float((int)x0f),
                        py - y0f, px - x0f);
    }
}

// ---------------- kernel 4: gather (fp16) + fp16 mma GEMM + BN + SiLU --------------
// 256 threads, tile = one ho row: 64 px x 128 co. 3 CTAs/SM.
// smem (bytes): As[0,17408) Bs[17408,52224) msh[52224,61440)
//               ssh[61440,+512) bsh[61952,+512)  total 62464
#define OFF_AS  0
#define OFF_BS  17408
#define OFF_MSH 52224
#define OFF_SSH 61440
#define OFF_BBH 61952
#define SMEM_MAIN 62464

// gather one pixel: lane covers 4 channels via LDG.64 (fp16); HFMA2 bilinear; STS.64
__device__ __forceinline__ void gather_px(int p, int pix, int lane,
                                          const float4* msh, const __half* xn, char* smc) {
    float4 m = msh[p * 64 + pix];
    int y0 = __float_as_int(m.x);
    int x0 = __float_as_int(m.y);
    float wy = m.z, wx = m.w;
    __half2 w00 = __float2half2_rn((1.f - wy) * (1.f - wx));
    __half2 w01 = __float2half2_rn((1.f - wy) * wx);
    __half2 w10 = __float2half2_rn(wy * (1.f - wx));
    __half2 w11 = __float2half2_rn(wy * wx);
    bool vy0 = (unsigned)y0       < (unsigned)HH;
    bool vy1 = (unsigned)(y0 + 1) < (unsigned)HH;
    bool vx0 = (unsigned)x0       < (unsigned)WW;
    bool vx1 = (unsigned)(x0 + 1) < (unsigned)WW;
    const __half* r0 = xn + (long long)y0 * (WW * CIN);
    const __half* r1 = r0 + WW * CIN;
    int ch0 = lane * 4;
    ull zz = 0ull;
    ull c00 = (vy0 && vx0) ? *(const ull*)&r0[x0 * CIN + ch0]       : zz;
    ull c01 = (vy0 && vx1) ? *(const ull*)&r0[(x0 + 1) * CIN + ch0] : zz;
    ull c10 = (vy1 && vx0) ? *(const ull*)&r1[x0 * CIN + ch0]       : zz;
    ull c11 = (vy1 && vx1) ? *(const ull*)&r1[(x0 + 1) * CIN + ch0] : zz;

    __half2 aL = __float2half2_rn(0.f), aH = aL;
    aL = __hfma2(w00, ((const __half2*)&c00)[0], aL);
    aH = __hfma2(w00, ((const __half2*)&c00)[1], aH);
    aL = __hfma2(w01, ((const __half2*)&c01)[0], aL);
    aH = __hfma2(w01, ((const __half2*)&c01)[1], aH);
    aL = __hfma2(w10, ((const __half2*)&c10)[0], aL);
    aH = __hfma2(w10, ((const __half2*)&c10)[1], aH);
    aL = __hfma2(w11, ((const __half2*)&c11)[0], aL);
    aH = __hfma2(w11, ((const __half2*)&c11)[1], aH);

    u32 lo = *(const u32*)&aL;
    u32 hi = *(const u32*)&aH;
    *(ull*)(smc + OFF_AS + pix * ROWB + ch0 * 2) = ((ull)hi << 32) | (ull)lo;
}

__device__ __forceinline__ void copy_bs(const __half* src_g, u32 dst_u, int tid) {
    const char* src = (const char*)src_g;
    #pragma unroll
    for (int i = 0; i < 8; i++) {            // 2048 16B-chunks / 256 thr
        int c   = tid + i * 256;
        int row = c >> 4;                    // cout row (256B per row)
        int c16 = c & 15;
        cp_async16(dst_u + (u32)(row * ROWB + c16 * 16), src + row * 256 + c16 * 16);
    }
}

__global__ __launch_bounds__(256, 3)
void k_main(const float* __restrict__ gamma,
            const float* __restrict__ beta,
            const float* __restrict__ rmean,
            const float* __restrict__ rvar,
            float* __restrict__ out) {
    extern __shared__ char smc[];
    float4* msh = (float4*)(smc + OFF_MSH);
    float*  ssh = (float*)(smc + OFF_SSH);
    float*  bsh = (float*)(smc + OFF_BBH);
    u32 sbase = cvta_smem(smc);
    u32 asU = sbase + OFF_AS;
    u32 bsU = sbase + OFF_BS;

    int tid  = threadIdx.x;
    int ho   = blockIdx.x;
    int n    = blockIdx.y;
    int lane = tid & 31;
    int warp = tid >> 5;
    int wm   = warp >> 2;          // 0..1 (32-pixel group)
    int wn   = warp & 3;           // 0..3 (32-cout group)
    int gpix0 = warp * 8;

    // stage metadata + BN params
    for (int i = tid; i < PP * 64; i += 256) {
        int p  = i >> 6;
        int wo = i & 63;
        msh[i] = g_meta[((size_t)(n * PP + p)) * PIX_PER_N + ho * WO + wo];
    }
    if (tid < COUT) {
        float s = gamma[tid] * rsqrtf(rvar[tid] + 1e-5f);
        ssh[tid] = s;
        bsh[tid] = beta[tid] - rmean[tid] * s;
    }
    __syncthreads();

    const __half* xn = g_xh + (size_t)n * HW * CIN;

    // prologue: Bs(0) async + gather tap 0
    copy_bs(g_wf, bsU, tid);
    CP_COMMIT();
    #pragma unroll 4
    for (int pl = 0; pl < 8; pl++)
        gather_px(0, gpix0 + pl, lane, msh, xn, smc);
    CP_WAIT(0);
    __syncthreads();

    float acc[2][4][4];
    #pragma unroll
    for (int mt = 0; mt < 2; mt++)
        #pragma unroll
        for (int nt = 0; nt < 4; nt++)
            #pragma unroll
            for (int i = 0; i < 4; i++) acc[mt][nt][i] = 0.f;

    int lrow = lane & 15;
    int lcol = (lane >> 4) << 4;

    for (int p = 0; p < PP; p++) {
        // ---- GEMM: 8 k16-steps, single-pass fp16 ----
        #pragma unroll
        for (int ks = 0; ks < 8; ks++) {
            u32 k0b = (u32)(ks * 32 + lcol);
            u32 a[2][4], b[2][4];
            #pragma unroll
            for (int mt = 0; mt < 2; mt++)
                ldm4(a[mt], asU + (u32)((wm * 32 + mt * 16 + lrow) * ROWB) + k0b);
            #pragma unroll
            for (int pr = 0; pr < 2; pr++)
                ldm4(b[pr], bsU + (u32)((wn * 32 + pr * 16 + lrow) * ROWB) + k0b);
            #pragma unroll
            for (int mt = 0; mt < 2; mt++)
                #pragma unroll
                for (int nt = 0; nt < 4; nt++) {
                    int pr = nt >> 1, s = nt & 1;
                    mma_f16(acc[mt][nt], a[mt], b[pr][s], b[pr][2 + s]);
                }
        }
        __syncthreads();                  // done reading As/Bs for tap p
        if (p < PP - 1) {
            copy_bs(g_wf + (size_t)(p + 1) * COUT * CIN, bsU, tid);
            CP_COMMIT();
            #pragma unroll 4
            for (int pl = 0; pl < 8; pl++)
                gather_px(p + 1, gpix0 + pl, lane, msh, xn, smc);
            CP_WAIT(0);
            __syncthreads();
        }
    }

    // ---- epilogue: BN + SiLU (fast sigmoid) ----
    #pragma unroll
    for (int mt = 0; mt < 2; mt++)
        #pragma unroll
        for (int nt = 0; nt < 4; nt++) {
            int co = wn * 32 + nt * 8 + (lane & 3) * 2;
            int px = wm * 32 + mt * 16 + (lane >> 2);
            float s0 = ssh[co],     b0 = bsh[co];
            float s1 = ssh[co + 1], b1 = bsh[co + 1];
            #pragma unroll
            for (int h = 0; h < 2; h++) {
                int wo = px + h * 8;                 // 0..63
                float y0v = acc[mt][nt][h * 2 + 0] * s0 + b0;
                float y1v = acc[mt][nt][h * 2 + 1] * s1 + b1;
                out[(((size_t)(n * COUT + co))     * HO + ho) * WO + wo] = y0v / (1.f + __expf(-y0v));
                out[(((size_t)(n * COUT + co + 1)) * HO + ho) * WO + wo] = y1v / (1.f + __expf(-y1v));
            }
        }
}

// ---------------- launch ----------------
extern "C" void kernel_launch(void* const* d_in, const int* in_sizes, int n_in,
                              void* d_out, int out_size) {
    const float* x        = (const float*)d_in[0];
    const float* offset_w = (const float*)d_in[1];
    const float* offset_b = (const float*)d_in[2];
    const float* deform_w = (const float*)d_in[3];
    const float* gamma    = (const float*)d_in[4];
    const float* beta     = (const float*)d_in[5];
    const float* rmean    = (const float*)d_in[6];
    const float* rvar     = (const float*)d_in[7];
    float* out = (float*)d_out;

    cudaFuncSetAttribute(k_offset_meta, cudaFuncAttributeMaxDynamicSharedMemorySize, 90000);
    cudaFuncSetAttribute(k_main,        cudaFuncAttributeMaxDynamicSharedMemorySize, SMEM_MAIN);

    k_transpose_x<<<dim3(HW / 32, CIN / 32, NB), dim3(32, 8)>>>(x);
    k_prep_w<<<(PP * COUT * CIN + 255) / 256, 256>>>(deform_w);

    size_t sm3 = (size_t)(PP * 9 * CIN) * 8 + (size_t)(8 * 72) * 4;  // 85248 B
    k_offset_meta<<<NB * PIX_PER_N / 32, 256, sm3>>>(offset_w, offset_b);

    k_main<<<dim3(HO, NB), 256, SMEM_MAIN>>>(gamma, beta, rmean, rvar, out);
}

// round 11
// speedup vs baseline: 2.4653x; 1.4050x over previous
#include <cuda_runtime.h>
#include <cuda_bf16.h>
#include <cuda_fp16.h>
#include <math.h>

typedef unsigned long long ull;
typedef unsigned int u32;

// Problem constants
#define NB   16
#define CIN  128
#define COUT 128
#define HH   64
#define WW   64
#define HO   64
#define WO   64
#define PP   9
#define HW   (HH*WW)
#define PIX_PER_N (HO*WO)

#define ROWB 272   // smem row stride (136 f16 = 17*16B, conflict-free ldmatrix)

// ---------------- scratch ----------------
__device__ __align__(16) __half g_xh[NB * HH * WW * CIN];   // NHWC x, fp16
__device__ __align__(16) __half g_wf[PP * COUT * CIN];      // [p][cout][cin] fp16 (deform)
__device__ __align__(16) __half g_wo[PP * 32 * CIN];        // [p][cout_pad32][cin] fp16 (offset)
__device__ uint4 g_mA[NB * PP * PIX_PER_N];                 // clamped byte offsets ry0,ry1,cx0,cx1
__device__ uint4 g_mW[NB * PP * PIX_PER_N];                 // half2 weights w00,w01,w10,w11

// ---------------- helpers ----------------
__device__ __forceinline__ u32 cvta_smem(const void* p) {
    u32 r;
    asm("{ .reg .u64 t; cvta.to.shared.u64 t, %1; cvt.u32.u64 %0, t; }" : "=r"(r) : "l"(p));
    return r;
}
__device__ __forceinline__ void ldm4(u32* r, u32 addr) {
    asm volatile("ldmatrix.sync.aligned.m8n8.x4.shared.b16 {%0,%1,%2,%3}, [%4];"
                 : "=r"(r[0]), "=r"(r[1]), "=r"(r[2]), "=r"(r[3]) : "r"(addr));
}
__device__ __forceinline__ void mma_f16(float* c, const u32* a, u32 b0, u32 b1) {
    asm volatile("mma.sync.aligned.m16n8k16.row.col.f32.f16.f16.f32 "
                 "{%0,%1,%2,%3}, {%4,%5,%6,%7}, {%8,%9}, {%0,%1,%2,%3};"
                 : "+f"(c[0]), "+f"(c[1]), "+f"(c[2]), "+f"(c[3])
                 : "r"(a[0]), "r"(a[1]), "r"(a[2]), "r"(a[3]), "r"(b0), "r"(b1));
}
__device__ __forceinline__ void cp_async16(u32 dst, const void* src) {
    asm volatile("cp.async.cg.shared.global [%0], [%1], 16;" :: "r"(dst), "l"(src));
}
__device__ __forceinline__ void cp_async16z(u32 dst, const void* src, u32 srcsz) {
    asm volatile("cp.async.cg.shared.global [%0], [%1], 16, %2;" :: "r"(dst), "l"(src), "r"(srcsz));
}
#define CP_COMMIT()  asm volatile("cp.async.commit_group;" ::: "memory")
#define CP_WAIT(n)   asm volatile("cp.async.wait_group %0;" :: "n"(n) : "memory")

// ---------------- kernel 1: x NCHW fp32 -> NHWC fp16 ----------------
__global__ void k_transpose_x(const float* __restrict__ x) {
    __shared__ float tile[32][33];
    int n   = blockIdx.z;
    int hw0 = blockIdx.x * 32;
    int c0  = blockIdx.y * 32;
    int tx = threadIdx.x, ty = threadIdx.y;
    #pragma unroll
    for (int i = 0; i < 32; i += 8)
        tile[ty + i][tx] = x[((size_t)(n * CIN + c0 + ty + i)) * HW + hw0 + tx];
    __syncthreads();
    #pragma unroll
    for (int i = 0; i < 32; i += 8)
        g_xh[((size_t)(n * HW + hw0 + ty + i)) * CIN + c0 + tx] =
            __float2half_rn(tile[tx][ty + i]);
}

// ---------------- kernel 2a: deform_w -> fp16 [p][cout][cin] ----------------
__global__ void k_prep_w(const float* __restrict__ w) {
    int i = blockIdx.x * 256 + threadIdx.x;
    if (i >= PP * COUT * CIN) return;
    int cin  = i & 127;
    int cout = (i >> 7) & 127;
    int p    = i >> 14;
    g_wf[i] = __float2half_rn(w[(cout * CIN + cin) * PP + p]);
}

// ---------------- kernel 2b: offset_w -> fp16 [p][32pad][cin] ----------------
__global__ void k_prep_wo(const float* __restrict__ w) {
    int i = blockIdx.x * 256 + threadIdx.x;
    if (i >= PP * 32 * CIN) return;
    int cin  = i & 127;
    int cout = (i >> 7) & 31;
    int p    = i >> 12;
    g_wo[i] = (cout < 18) ? __float2half_rn(w[(cout * CIN + cin) * PP + p])
                          : __ushort_as_half((unsigned short)0);
}

// ---------------- kernel 3: offset conv via fp16 mma + metadata ----------------
// 256 thr, tile 128 px (2 ho rows) x 32 co(pad), K=9x128.
// smem: As[0,34816) Bs[34816,43520) outs[43520,60416)  (outs stride 33 fl)
#define OFF2_AS  0
#define OFF2_BS  34816
#define OFF2_OUT 43520
#define SMEM_OFF 60416

__global__ __launch_bounds__(256, 3)
void k_offmma(const float* __restrict__ offset_b) {
    extern __shared__ char smc[];
    u32 sbase = cvta_smem(smc);
    u32 asU = sbase + OFF2_AS;
    u32 bsU = sbase + OFF2_BS;
    float* outs = (float*)(smc + OFF2_OUT);

    int tid  = threadIdx.x;
    int ho0  = blockIdx.x * 2;
    int n    = blockIdx.y;
    int lane = tid & 31;
    int warp = tid >> 5;
    int wm   = warp >> 1;      // 0..3 (32-px groups)
    int wn   = warp & 1;       // 0..1 (16-co groups)
    int lrow = lane & 15;
    int lcol = (lane >> 4) << 4;

    float acc[2][2][4];
    #pragma unroll
    for (int mt = 0; mt < 2; mt++)
        #pragma unroll
        for (int nt = 0; nt < 2; nt++)
            #pragma unroll
            for (int i = 0; i < 4; i++) acc[mt][nt][i] = 0.f;

    const __half* xn = g_xh + (size_t)n * HW * CIN;

    for (int p = 0; p < PP; p++) {
        int ky = p / 3 - 1, kx = p % 3 - 1;
        // As: im2col tile, 128 px x 256B, zero-fill OOB via src-size=0
        #pragma unroll
        for (int i = 0; i < 8; i++) {
            int c   = tid + i * 256;
            int pix = c >> 4, c16 = c & 15;
            int row = ho0 + (pix >> 6), wo = pix & 63;
            int ih = row + ky, iw = wo + kx;
            bool v = ((unsigned)ih < 64u) && ((unsigned)iw < 64u);
            int ihc = v ? ih : 0, iwc = v ? iw : 0;
            const char* src = (const char*)(xn + ((size_t)(ihc * WW + iwc)) * CIN) + c16 * 16;
            cp_async16z(asU + (u32)(pix * ROWB + c16 * 16), src, v ? 16u : 0u);
        }
        // Bs: 32 rows x 256B
        #pragma unroll
        for (int i = 0; i < 2; i++) {
            int c   = tid + i * 256;
            int row = c >> 4, c16 = c & 15;
            cp_async16(bsU + (u32)(row * ROWB + c16 * 16),
                       (const char*)(g_wo + p * 32 * CIN) + row * 256 + c16 * 16);
        }
        CP_COMMIT(); CP_WAIT(0);
        __syncthreads();

        #pragma unroll
        for (int ks = 0; ks < 8; ks++) {
            u32 k0b = (u32)(ks * 32 + lcol);
            u32 a[2][4], b[4];
            ldm4(a[0], asU + (u32)((wm * 32 + lrow) * ROWB) + k0b);
            ldm4(a[1], asU + (u32)((wm * 32 + 16 + lrow) * ROWB) + k0b);
            ldm4(b,    bsU + (u32)((wn * 16 + lrow) * ROWB) + k0b);
            #pragma unroll
            for (int mt = 0; mt < 2; mt++)
                #pragma unroll
                for (int nt = 0; nt < 2; nt++)
                    mma_f16(acc[mt][nt], a[mt], b[nt], b[2 + nt]);
        }
        __syncthreads();
    }

    // write acc -> outs[px][co] (stride 33)
    #pragma unroll
    for (int mt = 0; mt < 2; mt++)
        #pragma unroll
        for (int nt = 0; nt < 2; nt++) {
            int co = wn * 16 + nt * 8 + (lane & 3) * 2;
            int px = wm * 32 + mt * 16 + (lane >> 2);
            #pragma unroll
            for (int h = 0; h < 2; h++) {
                int pr = px + h * 8;
                outs[pr * 33 + co]     = acc[mt][nt][h * 2 + 0];
                outs[pr * 33 + co + 1] = acc[mt][nt][h * 2 + 1];
            }
        }
    __syncthreads();

    // metadata: clamped byte offsets + validity-folded half2 weights
    for (int it = tid; it < 128 * PP; it += 256) {
        int p   = it >> 7;
        int pix = it & 127;
        int row = ho0 + (pix >> 6), wo = pix & 63;
        float dy = outs[pix * 33 + 2 * p]     + offset_b[2 * p];
        float dx = outs[pix * 33 + 2 * p + 1] + offset_b[2 * p + 1];
        float py = dy + (float)(p / 3) + (float)(row - 1);
        float pxx = dx + (float)(p % 3) + (float)(wo - 1);
        float y0f = floorf(py), x0f = floorf(pxx);
        float wy = py - y0f, wx = pxx - x0f;
        int y0 = (int)y0f, x0 = (int)x0f;
        bool vy0 = (unsigned)y0       < 64u;
        bool vy1 = (unsigned)(y0 + 1) < 64u;
        bool vx0 = (unsigned)x0       < 64u;
        bool vx1 = (unsigned)(x0 + 1) < 64u;
        float w00 = (vy0 && vx0) ? (1.f - wy) * (1.f - wx) : 0.f;
        float w01 = (vy0 && vx1) ? (1.f - wy) * wx         : 0.f;
        float w10 = (vy1 && vx0) ? wy * (1.f - wx)         : 0.f;
        float w11 = (vy1 && vx1) ? wy * wx                 : 0.f;
        int y0c = min(max(y0, 0), 63),     y1c = min(max(y0 + 1, 0), 63);
        int x0c = min(max(x0, 0), 63),     x1c = min(max(x0 + 1, 0), 63);
        uint4 ma = make_uint4((u32)(y0c * (WW * CIN * 2)), (u32)(y1c * (WW * CIN * 2)),
                              (u32)(x0c * (CIN * 2)),      (u32)(x1c * (CIN * 2)));
        __half2 h00 = __float2half2_rn(w00);
        __half2 h01 = __float2half2_rn(w01);
        __half2 h10 = __float2half2_rn(w10);
        __half2 h11 = __float2half2_rn(w11);
        uint4 mw = make_uint4(*(u32*)&h00, *(u32*)&h01, *(u32*)&h10, *(u32*)&h11);
        size_t idx = ((size_t)(n * PP + p)) * PIX_PER_N + row * WO + wo;
        g_mA[idx] = ma;
        g_mW[idx] = mw;
    }
}

// ---------------- kernel 4: gather (precomputed meta) + fp16 mma + BN + SiLU -------
// 256 threads, tile = one ho row: 64 px x 128 co. 3 CTAs/SM.
// smem: As[0,17408) Bs[17408,52224) mshA[52224,61440) mshW[61440,70656)
//       ssh[70656,+512) bsh[71168,+512)  total 71680
#define OFF_AS   0
#define OFF_BS   17408
#define OFF_MSHA 52224
#define OFF_MSHW 61440
#define OFF_SSH  70656
#define OFF_BBH  71168
#define SMEM_MAIN 71680

__device__ __forceinline__ void gather_px(int p, int pix, int lane,
                                          const uint4* mshA, const uint4* mshW,
                                          const char* xb, char* smc) {
    uint4 ma = mshA[p * 64 + pix];
    uint4 mw = mshW[p * 64 + pix];
    int ch0 = lane * 4;
    const char* xc = xb + ch0 * 2;
    ull c00 = *(const ull*)(xc + ma.x + ma.z);
    ull c01 = *(const ull*)(xc + ma.x + ma.w);
    ull c10 = *(const ull*)(xc + ma.y + ma.z);
    ull c11 = *(const ull*)(xc + ma.y + ma.w);
    __half2 w00 = *(__half2*)&mw.x;
    __half2 w01 = *(__half2*)&mw.y;
    __half2 w10 = *(__half2*)&mw.z;
    __half2 w11 = *(__half2*)&mw.w;

    __half2 aL = __float2half2_rn(0.f), aH = aL;
    aL = __hfma2(w00, ((const __half2*)&c00)[0], aL);
    aH = __hfma2(w00, ((const __half2*)&c00)[1], aH);
    aL = __hfma2(w01, ((const __half2*)&c01)[0], aL);
    aH = __hfma2(w01, ((const __half2*)&c01)[1], aH);
    aL = __hfma2(w10, ((const __half2*)&c10)[0], aL);
    aH = __hfma2(w10, ((const __half2*)&c10)[1], aH);
    aL = __hfma2(w11, ((const __half2*)&c11)[0], aL);
    aH = __hfma2(w11, ((const __half2*)&c11)[1], aH);

    u32 lo = *(const u32*)&aL;
    u32 hi = *(const u32*)&aH;
    *(ull*)(smc + OFF_AS + pix * ROWB + ch0 * 2) = ((ull)hi << 32) | (ull)lo;
}

__device__ __forceinline__ void copy_bs(const __half* src_g, u32 dst_u, int tid) {
    const char* src = (const char*)src_g;
    #pragma unroll
    for (int i = 0; i < 8; i++) {
        int c   = tid + i * 256;
        int row = c >> 4;
        int c16 = c & 15;
        cp_async16(dst_u + (u32)(row * ROWB + c16 * 16), src + row * 256 + c16 * 16);
    }
}

__global__ __launch_bounds__(256, 3)
void k_main(const float* __restrict__ gamma,
            const float* __restrict__ beta,
            const float* __restrict__ rmean,
            const float* __restrict__ rvar,
            float* __restrict__ out) {
    extern __shared__ char smc[];
    uint4* mshA = (uint4*)(smc + OFF_MSHA);
    uint4* mshW = (uint4*)(smc + OFF_MSHW);
    float* ssh  = (float*)(smc + OFF_SSH);
    float* bsh  = (float*)(smc + OFF_BBH);
    u32 sbase = cvta_smem(smc);
    u32 asU = sbase + OFF_AS;
    u32 bsU = sbase + OFF_BS;

    int tid  = threadIdx.x;
    int ho   = blockIdx.x;
    int n    = blockIdx.y;
    int lane = tid & 31;
    int warp = tid >> 5;
    int wm   = warp >> 2;
    int wn   = warp & 3;
    int gpix0 = warp * 8;

    // stage metadata + BN params
    for (int i = tid; i < PP * 64; i += 256) {
        int p  = i >> 6;
        int wo = i & 63;
        size_t idx = ((size_t)(n * PP + p)) * PIX_PER_N + ho * WO + wo;
        mshA[i] = g_mA[idx];
        mshW[i] = g_mW[idx];
    }
    if (tid < COUT) {
        float s = gamma[tid] * rsqrtf(rvar[tid] + 1e-5f);
        ssh[tid] = s;
        bsh[tid] = beta[tid] - rmean[tid] * s;
    }
    __syncthreads();

    const char* xb = (const char*)(g_xh + (size_t)n * HW * CIN);

    // prologue: Bs(0) async + gather tap 0
    copy_bs(g_wf, bsU, tid);
    CP_COMMIT();
    #pragma unroll 4
    for (int pl = 0; pl < 8; pl++)
        gather_px(0, gpix0 + pl, lane, mshA, mshW, xb, smc);
    CP_WAIT(0);
    __syncthreads();

    float acc[2][4][4];
    #pragma unroll
    for (int mt = 0; mt < 2; mt++)
        #pragma unroll
        for (int nt = 0; nt < 4; nt++)
            #pragma unroll
            for (int i = 0; i < 4; i++) acc[mt][nt][i] = 0.f;

    int lrow = lane & 15;
    int lcol = (lane >> 4) << 4;

    for (int p = 0; p < PP; p++) {
        #pragma unroll
        for (int ks = 0; ks < 8; ks++) {
            u32 k0b = (u32)(ks * 32 + lcol);
            u32 a[2][4], b[2][4];
            #pragma unroll
            for (int mt = 0; mt < 2; mt++)
                ldm4(a[mt], asU + (u32)((wm * 32 + mt * 16 + lrow) * ROWB) + k0b);
            #pragma unroll
            for (int pr = 0; pr < 2; pr++)
                ldm4(b[pr], bsU + (u32)((wn * 32 + pr * 16 + lrow) * ROWB) + k0b);
            #pragma unroll
            for (int mt = 0; mt < 2; mt++)
                #pragma unroll
                for (int nt = 0; nt < 4; nt++) {
                    int pr = nt >> 1, s = nt & 1;
                    mma_f16(acc[mt][nt], a[mt], b[pr][s], b[pr][2 + s]);
                }
        }
        __syncthreads();
        if (p < PP - 1) {
            copy_bs(g_wf + (size_t)(p + 1) * COUT * CIN, bsU, tid);
            CP_COMMIT();
            #pragma unroll 4
            for (int pl = 0; pl < 8; pl++)
                gather_px(p + 1, gpix0 + pl, lane, mshA, mshW, xb, smc);
            CP_WAIT(0);
            __syncthreads();
        }
    }

    // ---- epilogue: BN + SiLU ----
    #pragma unroll
    for (int mt = 0; mt < 2; mt++)
        #pragma unroll
        for (int nt = 0; nt < 4; nt++) {
            int co = wn * 32 + nt * 8 + (lane & 3) * 2;
            int px = wm * 32 + mt * 16 + (lane >> 2);
            float s0 = ssh[co],     b0 = bsh[co];
            float s1 = ssh[co + 1], b1 = bsh[co + 1];
            #pragma unroll
            for (int h = 0; h < 2; h++) {
                int wo = px + h * 8;
                float y0v = acc[mt][nt][h * 2 + 0] * s0 + b0;
                float y1v = acc[mt][nt][h * 2 + 1] * s1 + b1;
                out[(((size_t)(n * COUT + co))     * HO + ho) * WO + wo] = y0v / (1.f + __expf(-y0v));
                out[(((size_t)(n * COUT + co + 1)) * HO + ho) * WO + wo] = y1v / (1.f + __expf(-y1v));
            }
        }
}

// ---------------- launch ----------------
extern "C" void kernel_launch(void* const* d_in, const int* in_sizes, int n_in,
                              void* d_out, int out_size) {
    const float* x        = (const float*)d_in[0];
    const float* offset_w = (const float*)d_in[1];
    const float* offset_b = (const float*)d_in[2];
    const float* deform_w = (const float*)d_in[3];
    const float* gamma    = (const float*)d_in[4];
    const float* beta     = (const float*)d_in[5];
    const float* rmean    = (const float*)d_in[6];
    const float* rvar     = (const float*)d_in[7];
    float* out = (float*)d_out;

    cudaFuncSetAttribute(k_offmma, cudaFuncAttributeMaxDynamicSharedMemorySize, SMEM_OFF);
    cudaFuncSetAttribute(k_main,   cudaFuncAttributeMaxDynamicSharedMemorySize, SMEM_MAIN);

    k_transpose_x<<<dim3(HW / 32, CIN / 32, NB), dim3(32, 8)>>>(x);
    k_prep_w<<<(PP * COUT * CIN + 255) / 256, 256>>>(deform_w);
    k_prep_wo<<<(PP * 32 * CIN + 255) / 256, 256>>>(offset_w);

    k_offmma<<<dim3(HO / 2, NB), 256, SMEM_OFF>>>(offset_b);

    k_main<<<dim3(HO, NB), 256, SMEM_MAIN>>>(gamma, beta, rmean, rvar, out);
}

// round 12
// speedup vs baseline: 2.4943x; 1.0118x over previous
#include <cuda_runtime.h>
#include <cuda_bf16.h>
#include <cuda_fp16.h>
#include <math.h>

typedef unsigned long long ull;
typedef unsigned int u32;

// Problem constants
#define NB   16
#define CIN  128
#define COUT 128
#define HH   64
#define WW   64
#define HO   64
#define WO   64
#define PP   9
#define HW   (HH*WW)
#define PIX_PER_N (HO*WO)

#define ROWB 272   // smem row stride (136 f16 = 17*16B, conflict-free ldmatrix)

// ---------------- scratch ----------------
__device__ __align__(16) __half g_xh[NB * HH * WW * CIN];   // NHWC x, fp16
__device__ __align__(16) __half g_wf[PP * COUT * CIN];      // [p][cout][cin] fp16 (deform)
__device__ __align__(16) __half g_wo[PP * 32 * CIN];        // [p][cout_pad32][cin] fp16 (offset)
__device__ uint4 g_m[NB * PP * PIX_PER_N * 2];              // per idx: {ma, mw} interleaved

// ---------------- helpers ----------------
__device__ __forceinline__ u32 cvta_smem(const void* p) {
    u32 r;
    asm("{ .reg .u64 t; cvta.to.shared.u64 t, %1; cvt.u32.u64 %0, t; }" : "=r"(r) : "l"(p));
    return r;
}
__device__ __forceinline__ void ldm4(u32* r, u32 addr) {
    asm volatile("ldmatrix.sync.aligned.m8n8.x4.shared.b16 {%0,%1,%2,%3}, [%4];"
                 : "=r"(r[0]), "=r"(r[1]), "=r"(r[2]), "=r"(r[3]) : "r"(addr));
}
__device__ __forceinline__ void mma_f16(float* c, const u32* a, u32 b0, u32 b1) {
    asm volatile("mma.sync.aligned.m16n8k16.row.col.f32.f16.f16.f32 "
                 "{%0,%1,%2,%3}, {%4,%5,%6,%7}, {%8,%9}, {%0,%1,%2,%3};"
                 : "+f"(c[0]), "+f"(c[1]), "+f"(c[2]), "+f"(c[3])
                 : "r"(a[0]), "r"(a[1]), "r"(a[2]), "r"(a[3]), "r"(b0), "r"(b1));
}
__device__ __forceinline__ void cp_async16(u32 dst, const void* src) {
    asm volatile("cp.async.cg.shared.global [%0], [%1], 16;" :: "r"(dst), "l"(src));
}
__device__ __forceinline__ void cp_async16z(u32 dst, const void* src, u32 srcsz) {
    asm volatile("cp.async.cg.shared.global [%0], [%1], 16, %2;" :: "r"(dst), "l"(src), "r"(srcsz));
}
#define CP_COMMIT()  asm volatile("cp.async.commit_group;" ::: "memory")
#define CP_WAIT(n)   asm volatile("cp.async.wait_group %0;" :: "n"(n) : "memory")

// ---------------- kernel 1: x NCHW fp32 -> NHWC fp16 ----------------
__global__ void k_transpose_x(const float* __restrict__ x) {
    __shared__ float tile[32][33];
    int n   = blockIdx.z;
    int hw0 = blockIdx.x * 32;
    int c0  = blockIdx.y * 32;
    int tx = threadIdx.x, ty = threadIdx.y;
    #pragma unroll
    for (int i = 0; i < 32; i += 8)
        tile[ty + i][tx] = x[((size_t)(n * CIN + c0 + ty + i)) * HW + hw0 + tx];
    __syncthreads();
    #pragma unroll
    for (int i = 0; i < 32; i += 8)
        g_xh[((size_t)(n * HW + hw0 + ty + i)) * CIN + c0 + tx] =
            __float2half_rn(tile[tx][ty + i]);
}

// ---------------- kernel 2a: deform_w -> fp16 [p][cout][cin] ----------------
__global__ void k_prep_w(const float* __restrict__ w) {
    int i = blockIdx.x * 256 + threadIdx.x;
    if (i >= PP * COUT * CIN) return;
    int cin  = i & 127;
    int cout = (i >> 7) & 127;
    int p    = i >> 14;
    g_wf[i] = __float2half_rn(w[(cout * CIN + cin) * PP + p]);
}

// ---------------- kernel 2b: offset_w -> fp16 [p][32pad][cin] ----------------
__global__ void k_prep_wo(const float* __restrict__ w) {
    int i = blockIdx.x * 256 + threadIdx.x;
    if (i >= PP * 32 * CIN) return;
    int cin  = i & 127;
    int cout = (i >> 7) & 31;
    int p    = i >> 12;
    g_wo[i] = (cout < 18) ? __float2half_rn(w[(cout * CIN + cin) * PP + p])
                          : __ushort_as_half((unsigned short)0);
}

// ---------------- kernel 3: offset conv via fp16 mma (pipelined) + metadata --------
// 256 thr, tile 128 px (2 ho rows) x 32 co(pad), K=9x128. Double-buffered groups.
// group buf: [As 34816][Bs 8704] = 43520; outs at 87040 (stride 33 floats)
#define OB_STRIDE 43520
#define OFF2_OUT  87040
#define SMEM_OFF  103936

__device__ __forceinline__ void off_issue_group(int p, int buf, int tid, int ho0,
                                                const __half* xn, u32 sbase) {
    u32 asb = sbase + buf * OB_STRIDE;
    u32 bsb = asb + 34816;
    int ky = p / 3 - 1, kx = p % 3 - 1;
    #pragma unroll
    for (int i = 0; i < 8; i++) {
        int c   = tid + i * 256;
        int pix = c >> 4, c16 = c & 15;
        int row = ho0 + (pix >> 6), wo = pix & 63;
        int ih = row + ky, iw = wo + kx;
        bool v = ((unsigned)ih < 64u) && ((unsigned)iw < 64u);
        int ihc = v ? ih : 0, iwc = v ? iw : 0;
        const char* src = (const char*)(xn + ((size_t)(ihc * WW + iwc)) * CIN) + c16 * 16;
        cp_async16z(asb + (u32)(pix * ROWB + c16 * 16), src, v ? 16u : 0u);
    }
    #pragma unroll
    for (int i = 0; i < 2; i++) {
        int c   = tid + i * 256;
        int row = c >> 4, c16 = c & 15;
        cp_async16(bsb + (u32)(row * ROWB + c16 * 16),
                   (const char*)(g_wo + p * 32 * CIN) + row * 256 + c16 * 16);
    }
    CP_COMMIT();
}

__global__ __launch_bounds__(256, 2)
void k_offmma(const float* __restrict__ offset_b) {
    extern __shared__ char smc[];
    u32 sbase = cvta_smem(smc);
    float* outs = (float*)(smc + OFF2_OUT);

    int tid  = threadIdx.x;
    int ho0  = blockIdx.x * 2;
    int n    = blockIdx.y;
    int lane = tid & 31;
    int warp = tid >> 5;
    int wm   = warp >> 1;      // 0..3 (32-px groups)
    int wn   = warp & 1;       // 0..1 (16-co groups)
    int lrow = lane & 15;
    int lcol = (lane >> 4) << 4;

    float acc[2][2][4];
    #pragma unroll
    for (int mt = 0; mt < 2; mt++)
        #pragma unroll
        for (int nt = 0; nt < 2; nt++)
            #pragma unroll
            for (int i = 0; i < 4; i++) acc[mt][nt][i] = 0.f;

    const __half* xn = g_xh + (size_t)n * HW * CIN;

    off_issue_group(0, 0, tid, ho0, xn, sbase);

    for (int p = 0; p < PP; p++) {
        if (p < PP - 1) {
            off_issue_group(p + 1, (p + 1) & 1, tid, ho0, xn, sbase);
            CP_WAIT(1);
        } else {
            CP_WAIT(0);
        }
        __syncthreads();

        u32 asU = sbase + (p & 1) * OB_STRIDE;
        u32 bsU = asU + 34816;
        #pragma unroll
        for (int ks = 0; ks < 8; ks++) {
            u32 k0b = (u32)(ks * 32 + lcol);
            u32 a[2][4], b[4];
            ldm4(a[0], asU + (u32)((wm * 32 + lrow) * ROWB) + k0b);
            ldm4(a[1], asU + (u32)((wm * 32 + 16 + lrow) * ROWB) + k0b);
            ldm4(b,    bsU + (u32)((wn * 16 + lrow) * ROWB) + k0b);
            #pragma unroll
            for (int mt = 0; mt < 2; mt++)
                #pragma unroll
                for (int nt = 0; nt < 2; nt++)
                    mma_f16(acc[mt][nt], a[mt], b[nt], b[2 + nt]);
        }
        __syncthreads();
    }

    // write acc -> outs[px][co] (stride 33)
    #pragma unroll
    for (int mt = 0; mt < 2; mt++)
        #pragma unroll
        for (int nt = 0; nt < 2; nt++) {
            int co = wn * 16 + nt * 8 + (lane & 3) * 2;
            int px = wm * 32 + mt * 16 + (lane >> 2);
            #pragma unroll
            for (int h = 0; h < 2; h++) {
                int pr = px + h * 8;
                outs[pr * 33 + co]     = acc[mt][nt][h * 2 + 0];
                outs[pr * 33 + co + 1] = acc[mt][nt][h * 2 + 1];
            }
        }
    __syncthreads();

    // metadata: clamped byte offsets + validity-folded half2 weights (combined stream)
    for (int it = tid; it < 128 * PP; it += 256) {
        int p   = it >> 7;
        int pix = it & 127;
        int row = ho0 + (pix >> 6), wo = pix & 63;
        float dy = outs[pix * 33 + 2 * p]     + offset_b[2 * p];
        float dx = outs[pix * 33 + 2 * p + 1] + offset_b[2 * p + 1];
        float py = dy + (float)(p / 3) + (float)(row - 1);
        float pxx = dx + (float)(p % 3) + (float)(wo - 1);
        float y0f = floorf(py), x0f = floorf(pxx);
        float wy = py - y0f, wx = pxx - x0f;
        int y0 = (int)y0f, x0 = (int)x0f;
        bool vy0 = (unsigned)y0       < 64u;
        bool vy1 = (unsigned)(y0 + 1) < 64u;
        bool vx0 = (unsigned)x0       < 64u;
        bool vx1 = (unsigned)(x0 + 1) < 64u;
        float w00 = (vy0 && vx0) ? (1.f - wy) * (1.f - wx) : 0.f;
        float w01 = (vy0 && vx1) ? (1.f - wy) * wx         : 0.f;
        float w10 = (vy1 && vx0) ? wy * (1.f - wx)         : 0.f;
        float w11 = (vy1 && vx1) ? wy * wx                 : 0.f;
        int y0c = min(max(y0, 0), 63),     y1c = min(max(y0 + 1, 0), 63);
        int x0c = min(max(x0, 0), 63),     x1c = min(max(x0 + 1, 0), 63);
        uint4 ma = make_uint4((u32)(y0c * (WW * CIN * 2)), (u32)(y1c * (WW * CIN * 2)),
                              (u32)(x0c * (CIN * 2)),      (u32)(x1c * (CIN * 2)));
        __half2 h00 = __float2half2_rn(w00);
        __half2 h01 = __float2half2_rn(w01);
        __half2 h10 = __float2half2_rn(w10);
        __half2 h11 = __float2half2_rn(w11);
        uint4 mw = make_uint4(*(u32*)&h00, *(u32*)&h01, *(u32*)&h10, *(u32*)&h11);
        size_t idx = ((size_t)(n * PP + p)) * PIX_PER_N + row * WO + wo;
        g_m[2 * idx]     = ma;
        g_m[2 * idx + 1] = mw;
    }
}

// ---------------- kernel 4: pipelined gather + fp16 mma + BN + SiLU ----------------
// 256 threads, tile = one ho row: 64 px x 128 co. 3 CTAs/SM.
// smem: As[2][17408] at 0, Bs at 34816, meta[2][2048] at 69632,
//       ssh at 73728, bsh at 74240  -> total 74752
#define OFF_AS   0
#define OFF_BS   34816
#define OFF_M    69632
#define OFF_SSH  73728
#define OFF_BBH  74240
#define SMEM_MAIN 74752

__device__ __forceinline__ void gather_px(int buf, int pix, int lane,
                                          const char* smc, const char* xb, char* smw) {
    const uint4* meta = (const uint4*)(smc + OFF_M + buf * 2048);
    uint4 ma = meta[2 * pix];
    uint4 mw = meta[2 * pix + 1];
    int ch0 = lane * 4;
    const char* xc = xb + ch0 * 2;
    ull c00 = *(const ull*)(xc + ma.x + ma.z);
    ull c01 = *(const ull*)(xc + ma.x + ma.w);
    ull c10 = *(const ull*)(xc + ma.y + ma.z);
    ull c11 = *(const ull*)(xc + ma.y + ma.w);
    __half2 w00 = *(__half2*)&mw.x;
    __half2 w01 = *(__half2*)&mw.y;
    __half2 w10 = *(__half2*)&mw.z;
    __half2 w11 = *(__half2*)&mw.w;

    __half2 aL = __float2half2_rn(0.f), aH = aL;
    aL = __hfma2(w00, ((const __half2*)&c00)[0], aL);
    aH = __hfma2(w00, ((const __half2*)&c00)[1], aH);
    aL = __hfma2(w01, ((const __half2*)&c01)[0], aL);
    aH = __hfma2(w01, ((const __half2*)&c01)[1], aH);
    aL = __hfma2(w10, ((const __half2*)&c10)[0], aL);
    aH = __hfma2(w10, ((const __half2*)&c10)[1], aH);
    aL = __hfma2(w11, ((const __half2*)&c11)[0], aL);
    aH = __hfma2(w11, ((const __half2*)&c11)[1], aH);

    u32 lo = *(const u32*)&aL;
    u32 hi = *(const u32*)&aH;
    *(ull*)(smw + OFF_AS + buf * 17408 + pix * ROWB + ch0 * 2) = ((ull)hi << 32) | (ull)lo;
}

__device__ __forceinline__ void copy_bs(const __half* src_g, u32 dst_u, int tid) {
    const char* src = (const char*)src_g;
    #pragma unroll
    for (int i = 0; i < 8; i++) {
        int c   = tid + i * 256;
        int row = c >> 4;
        int c16 = c & 15;
        cp_async16(dst_u + (u32)(row * ROWB + c16 * 16), src + row * 256 + c16 * 16);
    }
}

__global__ __launch_bounds__(256, 3)
void k_main(const float* __restrict__ gamma,
            const float* __restrict__ beta,
            const float* __restrict__ rmean,
            const float* __restrict__ rvar,
            float* __restrict__ out) {
    extern __shared__ char smc[];
    float* ssh  = (float*)(smc + OFF_SSH);
    float* bsh  = (float*)(smc + OFF_BBH);
    u32 sbase = cvta_smem(smc);
    u32 asU = sbase + OFF_AS;
    u32 bsU = sbase + OFF_BS;
    u32 mU  = sbase + OFF_M;

    int tid  = threadIdx.x;
    int ho   = blockIdx.x;
    int n    = blockIdx.y;
    int lane = tid & 31;
    int warp = tid >> 5;
    int wm   = warp >> 2;
    int wn   = warp & 3;
    int gpix0 = warp * 8;

    // meta src base for tap p: g_m + 2 * ((n*PP+p)*PIX_PER_N + ho*WO)
    const char* mbase0 = (const char*)(g_m + 2 * (((size_t)(n * PP)) * PIX_PER_N + ho * WO));
    const size_t mstride = (size_t)PIX_PER_N * 32;   // bytes per tap step

    if (tid < COUT) {
        float s = gamma[tid] * rsqrtf(rvar[tid] + 1e-5f);
        ssh[tid] = s;
        bsh[tid] = beta[tid] - rmean[tid] * s;
    }

    const char* xb = (const char*)(g_xh + (size_t)n * HW * CIN);

    // prologue: meta(0) + Bs(0); wait; gather(0); meta(1); wait
    if (tid < 128) cp_async16(mU + tid * 16, mbase0 + tid * 16);
    copy_bs(g_wf, bsU, tid);
    CP_COMMIT();
    CP_WAIT(0);
    __syncthreads();
    #pragma unroll 4
    for (int pl = 0; pl < 8; pl++)
        gather_px(0, gpix0 + pl, lane, smc, xb, smc);
    if (tid < 128) cp_async16(mU + 2048 + tid * 16, mbase0 + mstride + tid * 16);
    CP_COMMIT();
    CP_WAIT(0);
    __syncthreads();

    float acc[2][4][4];
    #pragma unroll
    for (int mt = 0; mt < 2; mt++)
        #pragma unroll
        for (int nt = 0; nt < 4; nt++)
            #pragma unroll
            for (int i = 0; i < 4; i++) acc[mt][nt][i] = 0.f;

    int lrow = lane & 15;
    int lcol = (lane >> 4) << 4;

    for (int p = 0; p < PP; p++) {
        // issue meta(p+2) into mbuf(p&1); gather(p+1) into As buf (p+1)&1
        if (p <= PP - 3) {
            if (tid < 128)
                cp_async16(mU + (p & 1) * 2048 + tid * 16,
                           mbase0 + (size_t)(p + 2) * mstride + tid * 16);
            CP_COMMIT();
        }
        if (p <= PP - 2) {
            #pragma unroll 4
            for (int pl = 0; pl < 8; pl++)
                gather_px((p + 1) & 1, gpix0 + pl, lane, smc, xb, smc);
        }

        // ---- GEMM tap p from As buf (p&1) ----
        u32 asb = asU + (u32)((p & 1) * 17408);
        #pragma unroll
        for (int ks = 0; ks < 8; ks++) {
            u32 k0b = (u32)(ks * 32 + lcol);
            u32 a[2][4], b[2][4];
            #pragma unroll
            for (int mt = 0; mt < 2; mt++)
                ldm4(a[mt], asb + (u32)((wm * 32 + mt * 16 + lrow) * ROWB) + k0b);
            #pragma unroll
            for (int pr = 0; pr < 2; pr++)
                ldm4(b[pr], bsU + (u32)((wn * 32 + pr * 16 + lrow) * ROWB) + k0b);
            #pragma unroll
            for (int mt = 0; mt < 2; mt++)
                #pragma unroll
                for (int nt = 0; nt < 4; nt++) {
                    int pr = nt >> 1, s = nt & 1;
                    mma_f16(acc[mt][nt], a[mt], b[pr][s], b[pr][2 + s]);
                }
        }
        __syncthreads();                 // done reading Bs(p) + As(p&1); gather STS drained
        if (p <= PP - 2) {
            copy_bs(g_wf + (size_t)(p + 1) * COUT * CIN, bsU, tid);
            CP_COMMIT();
            CP_WAIT(0);
            __syncthreads();
        }
    }

    // ---- epilogue: BN + SiLU ----
    #pragma unroll
    for (int mt = 0; mt < 2; mt++)
        #pragma unroll
        for (int nt = 0; nt < 4; nt++) {
            int co = wn * 32 + nt * 8 + (lane & 3) * 2;
            int px = wm * 32 + mt * 16 + (lane >> 2);
            float s0 = ssh[co],     b0 = bsh[co];
            float s1 = ssh[co + 1], b1 = bsh[co + 1];
            #pragma unroll
            for (int h = 0; h < 2; h++) {
                int wo = px + h * 8;
                float y0v = acc[mt][nt][h * 2 + 0] * s0 + b0;
                float y1v = acc[mt][nt][h * 2 + 1] * s1 + b1;
                out[(((size_t)(n * COUT + co))     * HO + ho) * WO + wo] = y0v / (1.f + __expf(-y0v));
                out[(((size_t)(n * COUT + co + 1)) * HO + ho) * WO + wo] = y1v / (1.f + __expf(-y1v));
            }
        }
}

// ---------------- launch ----------------
extern "C" void kernel_launch(void* const* d_in, const int* in_sizes, int n_in,
                              void* d_out, int out_size) {
    const float* x        = (const float*)d_in[0];
    const float* offset_w = (const float*)d_in[1];
    const float* offset_b = (const float*)d_in[2];
    const float* deform_w = (const float*)d_in[3];
    const float* gamma    = (const float*)d_in[4];
    const float* beta     = (const float*)d_in[5];
    const float* rmean    = (const float*)d_in[6];
    const float* rvar     = (const float*)d_in[7];
    float* out = (float*)d_out;

    cudaFuncSetAttribute(k_offmma, cudaFuncAttributeMaxDynamicSharedMemorySize, SMEM_OFF);
    cudaFuncSetAttribute(k_main,   cudaFuncAttributeMaxDynamicSharedMemorySize, SMEM_MAIN);

    k_transpose_x<<<dim3(HW / 32, CIN / 32, NB), dim3(32, 8)>>>(x);
    k_prep_w<<<(PP * COUT * CIN + 255) / 256, 256>>>(deform_w);
    k_prep_wo<<<(PP * 32 * CIN + 255) / 256, 256>>>(offset_w);

    k_offmma<<<dim3(HO / 2, NB), 256, SMEM_OFF>>>(offset_b);

    k_main<<<dim3(HO, NB), 256, SMEM_MAIN>>>(gamma, beta, rmean, rvar, out);
}